// round 2
// baseline (speedup 1.0000x reference)
#include <cuda_runtime.h>
#include <math.h>

#define Nn 16384
#define Ee 262144
#define Cc 256
#define Rr 9
#define Bb 4
#define NK (Nn*Rr)          /* 147456 per-(node,rel) segments */
#define NCHUNK (NK/1024)    /* 144 scan chunks */
#define MAXTILES (Ee/64 + Rr) /* 4105 */

// ---------------- static scratch (allowed: __device__ globals) ----------------
__device__ float g_W[4][Rr*Cc*Cc];      // 0:s2r 1:o2r 2:r2s 3:r2o
__device__ float g_v[2][Rr*Cc];         // W[r]@aw[r] per branch (0:sub 1:obj)
__device__ float g_scores[2][Ee];
__device__ int   g_counts[2][NK];
__device__ int   g_rowptr[2][NK+1];
__device__ int   g_cursor[2][NK];
__device__ int   g_elist[2][Ee];
__device__ int   g_partials[2][NCHUNK];
__device__ float g_P[(size_t)NK*Cc];    // one branch at a time (151MB)
__device__ float g_invdiv[2][Nn];
__device__ int   g_binCount[2][Rr];
__device__ int   g_binStart[2][Rr+1];
__device__ int   g_tileStart[2][Rr+1];
__device__ int   g_binCursor[2][Rr];
__device__ int   g_perm[2][Ee];

// ---------------- init ----------------
__global__ void k_init() {
    int i = blockIdx.x*256 + threadIdx.x;
    if (i < 2*NK) ((int*)g_counts)[i] = 0;
    if (i < 2*Rr) ((int*)g_binCount)[i] = 0;
}

// W[branch][r] = sum_b att[r,b]*basis[b]
__global__ void k_w(const float* b0, const float* a0, const float* b1, const float* a1,
                    const float* b2, const float* a2, const float* b3, const float* a3) {
    int bx = blockIdx.x;
    int br = bx / (Rr*Cc);
    int rem = bx % (Rr*Cc);
    int r = rem / Cc, i = rem % Cc, j = threadIdx.x;
    const float* bas = (br==0)?b0:(br==1)?b1:(br==2)?b2:b3;
    const float* att = (br==0)?a0:(br==1)?a1:(br==2)?a2:a3;
    float w = 0.f;
#pragma unroll
    for (int b = 0; b < Bb; b++) w += att[r*Bb+b]*bas[(b*Cc+i)*Cc + j];
    g_W[br][(r*Cc+i)*Cc + j] = w;
}

// v[br][r][i] = sum_j W[2+br][r][i][j]*aw[r][j]
__global__ void k_v(const float* aw_sub, const float* aw_obj) {
    int br = blockIdx.x / Rr, r = blockIdx.x % Rr;
    const float* aw = (br==0) ? aw_sub : aw_obj;
    const float* W = g_W[2+br] + r*Cc*Cc;
    int i = threadIdx.x;
    float s = 0.f;
    for (int j = 0; j < Cc; j++) s += W[i*Cc+j]*aw[r*Cc+j];
    g_v[br][r*Cc+i] = s;
}

// relation-bin hist + per-(node,rel) key counts
__global__ void k_hist(const int* src, const int* dst, const int* et_rel, const int* et_inv) {
    __shared__ int h[2][Rr];
    int tid = threadIdx.x;
    if (tid < 2*Rr) ((int*)h)[tid] = 0;
    __syncthreads();
#pragma unroll
    for (int u = 0; u < 4; u++) {
        int e = blockIdx.x*1024 + u*256 + tid;
        int r1 = et_rel[e], r2 = et_inv[e];
        atomicAdd(&h[0][r1], 1); atomicAdd(&h[1][r2], 1);
        atomicAdd(&g_counts[0][src[e]*Rr + r2], 1);   // rel2sub: seg=src, type=inv
        atomicAdd(&g_counts[1][dst[e]*Rr + r1], 1);   // rel2obj: seg=dst, type=fwd
    }
    __syncthreads();
    if (tid < Rr) {
        atomicAdd(&g_binCount[0][tid], h[0][tid]);
        atomicAdd(&g_binCount[1][tid], h[1][tid]);
    }
}

__global__ void k_smallscan() {
    int br = threadIdx.x;
    if (br < 2) {
        int s = 0, t = 0;
        for (int r = 0; r < Rr; r++) {
            g_binStart[br][r] = s; g_tileStart[br][r] = t; g_binCursor[br][r] = s;
            int c = g_binCount[br][r];
            s += c; t += (c + 63)/64;
        }
        g_binStart[br][Rr] = s; g_tileStart[br][Rr] = t;
    }
}

// block-aggregated scatter into relation-sorted perms
__global__ void k_binscatter(const int* et_rel, const int* et_inv) {
    __shared__ int h[2][Rr], base[2][Rr], loc[2][Rr];
    int tid = threadIdx.x;
    if (tid < 2*Rr) { ((int*)h)[tid] = 0; ((int*)loc)[tid] = 0; }
    __syncthreads();
    int es[4], r1s[4], r2s[4];
#pragma unroll
    for (int u = 0; u < 4; u++) {
        int e = blockIdx.x*1024 + u*256 + tid;
        es[u] = e; r1s[u] = et_rel[e]; r2s[u] = et_inv[e];
        atomicAdd(&h[0][r1s[u]], 1); atomicAdd(&h[1][r2s[u]], 1);
    }
    __syncthreads();
    if (tid < Rr) {
        base[0][tid] = atomicAdd(&g_binCursor[0][tid], h[0][tid]);
        base[1][tid] = atomicAdd(&g_binCursor[1][tid], h[1][tid]);
    }
    __syncthreads();
#pragma unroll
    for (int u = 0; u < 4; u++) {
        int p0 = base[0][r1s[u]] + atomicAdd(&loc[0][r1s[u]], 1);
        g_perm[0][p0] = es[u];
        int p1 = base[1][r2s[u]] + atomicAdd(&loc[1][r2s[u]], 1);
        g_perm[1][p1] = es[u];
    }
}

// 3-phase exclusive scan of key counts -> rowptr
__global__ void k_scan1() {
    int br = blockIdx.x / NCHUNK, ch = blockIdx.x % NCHUNK;
    int tid = threadIdx.x;
    int basei = ch*1024 + tid*4;
    int v[4]; int t = 0;
#pragma unroll
    for (int i = 0; i < 4; i++) { v[i] = g_counts[br][basei+i]; t += v[i]; }
    __shared__ int s[256];
    s[tid] = t; __syncthreads();
    for (int off = 1; off < 256; off <<= 1) {
        int x = (tid >= off) ? s[tid-off] : 0;
        __syncthreads();
        s[tid] += x;
        __syncthreads();
    }
    int excl = s[tid] - t;
#pragma unroll
    for (int i = 0; i < 4; i++) { g_rowptr[br][basei+i] = excl; excl += v[i]; }
    if (tid == 255) g_partials[br][ch] = s[255];
}

__global__ void k_scan2() {
    int br = threadIdx.x;
    if (br < 2) {
        int run = 0;
        for (int c = 0; c < NCHUNK; c++) { int p = g_partials[br][c]; g_partials[br][c] = run; run += p; }
        g_rowptr[br][NK] = run;
    }
}

__global__ void k_scan3() {
    int br = blockIdx.x / NCHUNK, ch = blockIdx.x % NCHUNK;
    int add = g_partials[br][ch];
    int basei = ch*1024 + threadIdx.x*4;
#pragma unroll
    for (int i = 0; i < 4; i++) {
        int p = g_rowptr[br][basei+i] + add;
        g_rowptr[br][basei+i] = p;
        g_cursor[br][basei+i] = p;
    }
}

__global__ void k_csrscatter(const int* src, const int* dst, const int* et_rel, const int* et_inv) {
    int e = blockIdx.x*256 + threadIdx.x;
    int k0 = src[e]*Rr + et_inv[e];
    g_elist[0][atomicAdd(&g_cursor[0][k0], 1)] = e;
    int k1 = dst[e]*Rr + et_rel[e];
    g_elist[1][atomicAdd(&g_cursor[1][k1], 1)] = e;
}

// per-node inverse relation-presence divisor (per branch)
__global__ void k_invdiv() {
    int n = blockIdx.x*256 + threadIdx.x;
#pragma unroll
    for (int br = 0; br < 2; br++) {
        int c = 0;
        for (int r = 0; r < Rr; r++)
            if (g_rowptr[br][n*Rr+r+1] > g_rowptr[br][n*Rr+r]) c++;
        g_invdiv[br][n] = c ? 1.f/(float)c : 1.f;
    }
}

// ---------------- edge gather-GEMM: rel_emb = ef + 0.5*(nf[src]@W_s2r + nf[dst]@W_o2r) ----------------
// MODE 0: s2r (perm by et_rel, gather src, write ef+0.5*acc)
// MODE 1: o2r (perm by et_inv, gather dst, += 0.5*acc)
template<int MODE>
__global__ void k_gemm_edge(const int* idx, const float* nf, const float* ef, float* rel_out) {
    const int br = MODE;
    int bx = blockIdx.x;
    if (bx >= g_tileStart[br][Rr]) return;
    int r = 0;
    while (bx >= g_tileStart[br][r+1]) r++;
    int row0 = g_binStart[br][r] + (bx - g_tileStart[br][r])*64;
    int rowEnd = g_binStart[br][r+1];
    int cb = blockIdx.y*64;
    const float* W = g_W[MODE] + r*Cc*Cc;

    __shared__ __align__(16) float As[16][68];
    __shared__ __align__(16) float Bs[16][64];
    __shared__ int es[64], gs[64];
    int tid = threadIdx.x;
    if (tid < 64) {
        int row = row0 + tid;
        if (row < rowEnd) { int e = g_perm[br][row]; es[tid] = e; gs[tid] = idx[e]; }
        else { es[tid] = -1; gs[tid] = 0; }
    }
    __syncthreads();

    int lm = tid >> 2, lk = (tid & 3)*4;     // A-load: row, k4
    int bk = tid >> 4, bj = (tid & 15)*4;    // B-load: k, col4
    int m0 = (tid >> 4)*4, n0 = (tid & 15)*4;

    float acc[4][4];
#pragma unroll
    for (int i = 0; i < 4; i++)
#pragma unroll
        for (int j = 0; j < 4; j++) acc[i][j] = 0.f;

    for (int kk = 0; kk < Cc; kk += 16) {
        float4 av = *(const float4*)(nf + (size_t)gs[lm]*Cc + kk + lk);
        As[lk+0][lm] = av.x; As[lk+1][lm] = av.y; As[lk+2][lm] = av.z; As[lk+3][lm] = av.w;
        *(float4*)&Bs[bk][bj] = *(const float4*)(W + (kk+bk)*Cc + cb + bj);
        __syncthreads();
#pragma unroll
        for (int k = 0; k < 16; k++) {
            float4 a = *(const float4*)&As[k][m0];
            float4 b = *(const float4*)&Bs[k][n0];
            float aa[4] = {a.x,a.y,a.z,a.w}, bb[4] = {b.x,b.y,b.z,b.w};
#pragma unroll
            for (int i = 0; i < 4; i++)
#pragma unroll
                for (int j = 0; j < 4; j++) acc[i][j] += aa[i]*bb[j];
        }
        __syncthreads();
    }

#pragma unroll
    for (int i = 0; i < 4; i++) {
        int e = es[m0 + i];
        if (e < 0) continue;
        float* o = rel_out + (size_t)e*Cc + cb + n0;
        if (MODE == 0) {
            float4 e4 = *(const float4*)(ef + (size_t)e*Cc + cb + n0);
            float4 w;
            w.x = e4.x + 0.5f*acc[i][0]; w.y = e4.y + 0.5f*acc[i][1];
            w.z = e4.z + 0.5f*acc[i][2]; w.w = e4.w + 0.5f*acc[i][3];
            *(float4*)o = w;
        } else {
            float4 cur = *(const float4*)o;
            cur.x += 0.5f*acc[i][0]; cur.y += 0.5f*acc[i][1];
            cur.z += 0.5f*acc[i][2]; cur.w += 0.5f*acc[i][3];
            *(float4*)o = cur;
        }
    }
}

// scores: score_e = leaky_relu(rel_emb_e . v[r] + b[r]) for both branches (one warp/edge)
__global__ void k_score(const float* rel, const int* et_rel, const int* et_inv,
                        const float* ab_sub, const float* ab_obj) {
    int w = (blockIdx.x*blockDim.x + threadIdx.x) >> 5;
    int lane = threadIdx.x & 31;
    if (w >= Ee) return;
    int e = w;
    int r1 = et_rel[e], r2 = et_inv[e];
    const float* x = rel + (size_t)e*Cc;
    const float* vs = g_v[0] + r2*Cc;
    const float* vo = g_v[1] + r1*Cc;
    float s0 = 0.f, s1 = 0.f;
#pragma unroll
    for (int i = 0; i < 8; i++) {
        float xv = x[i*32 + lane];
        s0 += xv*vs[i*32 + lane];
        s1 += xv*vo[i*32 + lane];
    }
#pragma unroll
    for (int o = 16; o > 0; o >>= 1) {
        s0 += __shfl_down_sync(0xffffffffu, s0, o);
        s1 += __shfl_down_sync(0xffffffffu, s1, o);
    }
    if (lane == 0) {
        float a = s0 + ab_sub[r2]; a = (a >= 0.f) ? a : 0.01f*a; g_scores[0][e] = a;
        float b = s1 + ab_obj[r1]; b = (b >= 0.f) ? b : 0.01f*b; g_scores[1][e] = b;
    }
}

// P[n,r,:] = softmax-weighted sum of rel_emb rows within (node, rel) segment (warp/key, no atomics)
__global__ void k_pfill(const float* rel, int br) {
    int w = blockIdx.x*8 + (threadIdx.x >> 5);
    int lane = threadIdx.x & 31;
    if (w >= NK) return;
    int lo = g_rowptr[br][w], hi = g_rowptr[br][w+1];
    float acc[8];
#pragma unroll
    for (int i = 0; i < 8; i++) acc[i] = 0.f;
    if (lo < hi) {
        float m = -1e30f;
        for (int p = lo; p < hi; p++) {
            float s = g_scores[br][g_elist[br][p]];
            m = fmaxf(m, s);
        }
        float den = 0.f;
        for (int p = lo; p < hi; p++) {
            int e = g_elist[br][p];
            float wt = expf(g_scores[br][e] - m);
            den += wt;
            const float* x = rel + (size_t)e*Cc;
#pragma unroll
            for (int i = 0; i < 8; i++) acc[i] += wt*x[i*32 + lane];
        }
        float inv = 1.f/den;
#pragma unroll
        for (int i = 0; i < 8; i++) acc[i] *= inv;
    }
    float* Pr = g_P + (size_t)w*Cc;
#pragma unroll
    for (int i = 0; i < 8; i++) Pr[i*32 + lane] = acc[i];
}

// agg GEMM: out[n] (=/+=) nf[n] + 0.5*invdiv[n]*sum_r P[n,r,:]@W[2+BR][r]
template<int BR>
__global__ void k_gemm3(const float* nf, float* node_out) {
    int n0b = blockIdx.x*64;
    int cb = blockIdx.y*64;
    const float* Wbase = g_W[2+BR];
    __shared__ __align__(16) float As[16][68];
    __shared__ __align__(16) float Bs[16][64];
    int tid = threadIdx.x;
    int lm = tid >> 2, lk = (tid & 3)*4;
    int bk = tid >> 4, bj = (tid & 15)*4;
    int m0 = (tid >> 4)*4, n0 = (tid & 15)*4;
    float acc[4][4];
#pragma unroll
    for (int i = 0; i < 4; i++)
#pragma unroll
        for (int j = 0; j < 4; j++) acc[i][j] = 0.f;

    for (int r = 0; r < Rr; r++) {
        const float* W = Wbase + r*Cc*Cc;
        for (int kk = 0; kk < Cc; kk += 16) {
            float4 av = *(const float4*)(g_P + (size_t)(n0b+lm)*(Rr*Cc) + r*Cc + kk + lk);
            As[lk+0][lm] = av.x; As[lk+1][lm] = av.y; As[lk+2][lm] = av.z; As[lk+3][lm] = av.w;
            *(float4*)&Bs[bk][bj] = *(const float4*)(W + (kk+bk)*Cc + cb + bj);
            __syncthreads();
#pragma unroll
            for (int k = 0; k < 16; k++) {
                float4 a = *(const float4*)&As[k][m0];
                float4 b = *(const float4*)&Bs[k][n0];
                float aa[4] = {a.x,a.y,a.z,a.w}, bb[4] = {b.x,b.y,b.z,b.w};
#pragma unroll
                for (int i = 0; i < 4; i++)
#pragma unroll
                    for (int j = 0; j < 4; j++) acc[i][j] += aa[i]*bb[j];
            }
            __syncthreads();
        }
    }

#pragma unroll
    for (int i = 0; i < 4; i++) {
        int n = n0b + m0 + i;
        float sc = 0.5f*g_invdiv[BR][n];
        float* o = node_out + (size_t)n*Cc + cb + n0;
        if (BR == 0) {
            float4 nfv = *(const float4*)(nf + (size_t)n*Cc + cb + n0);
            float4 w;
            w.x = nfv.x + sc*acc[i][0]; w.y = nfv.y + sc*acc[i][1];
            w.z = nfv.z + sc*acc[i][2]; w.w = nfv.w + sc*acc[i][3];
            *(float4*)o = w;
        } else {
            float4 cur = *(const float4*)o;
            cur.x += sc*acc[i][0]; cur.y += sc*acc[i][1];
            cur.z += sc*acc[i][2]; cur.w += sc*acc[i][3];
            *(float4*)o = cur;
        }
    }
}

extern "C" void kernel_launch(void* const* d_in, const int* in_sizes, int n_in,
                              void* d_out, int out_size) {
    const int* ei      = (const int*)d_in[0];
    const int* src     = ei;
    const int* dst     = ei + Ee;
    const float* nf    = (const float*)d_in[1];
    const float* ef    = (const float*)d_in[2];
    const int* et_rel  = (const int*)d_in[3];
    const int* et_inv  = (const int*)d_in[4];
    /* d_in[5] edge_norm: unused by reference */
    const float* s2r_b = (const float*)d_in[6];
    const float* s2r_a = (const float*)d_in[7];
    const float* o2r_b = (const float*)d_in[8];
    const float* o2r_a = (const float*)d_in[9];
    const float* r2s_b = (const float*)d_in[10];
    const float* r2s_a = (const float*)d_in[11];
    const float* r2s_w = (const float*)d_in[12];
    const float* r2s_bias = (const float*)d_in[13];
    const float* r2o_b = (const float*)d_in[14];
    const float* r2o_a = (const float*)d_in[15];
    const float* r2o_w = (const float*)d_in[16];
    const float* r2o_bias = (const float*)d_in[17];

    float* node_out = (float*)d_out;
    float* rel_out  = node_out + (size_t)Nn*Cc;

    k_init<<<(2*NK + 255)/256, 256>>>();
    k_w<<<4*Rr*Cc, 256>>>(s2r_b, s2r_a, o2r_b, o2r_a, r2s_b, r2s_a, r2o_b, r2o_a);
    k_v<<<2*Rr, 256>>>(r2s_w, r2o_w);
    k_hist<<<256, 256>>>(src, dst, et_rel, et_inv);
    k_smallscan<<<1, 32>>>();
    k_binscatter<<<256, 256>>>(et_rel, et_inv);
    k_scan1<<<2*NCHUNK, 256>>>();
    k_scan2<<<1, 32>>>();
    k_scan3<<<2*NCHUNK, 256>>>();
    k_csrscatter<<<Ee/256, 256>>>(src, dst, et_rel, et_inv);
    k_invdiv<<<Nn/256, 256>>>();

    dim3 ge(MAXTILES, 4);
    k_gemm_edge<0><<<ge, 256>>>(src, nf, ef, rel_out);
    k_gemm_edge<1><<<ge, 256>>>(dst, nf, ef, rel_out);

    k_score<<<Ee/8, 256>>>(rel_out, et_rel, et_inv, r2s_bias, r2o_bias);

    dim3 g3(Nn/64, 4);
    k_pfill<<<NK/8, 256>>>(rel_out, 0);
    k_gemm3<0><<<g3, 256>>>(nf, node_out);
    k_pfill<<<NK/8, 256>>>(rel_out, 1);
    k_gemm3<1><<<g3, 256>>>(nf, node_out);
}

// round 6
// speedup vs baseline: 2.0618x; 2.0618x over previous
#include <cuda_runtime.h>
#include <cuda_bf16.h>
#include <math.h>
#include <stdint.h>

#define Nn 16384
#define Ee 262144
#define Cc 256
#define Rr 9
#define Bb 4
#define NK (Nn*Rr)
#define NCHUNK (NK/1024)
#define TILE_M 128
#define MAXTILES (Ee/TILE_M + Rr)   /* 2057 */

#define PADK 40                     /* padded bf16 cols per 32-col chunk row */
#define PART_ELE (128*PADK)         /* 5120 bf16 = 10240 B */
#define SM_BASE 1024
#define SM_TOTAL (SM_BASE + 8*PART_ELE*2)   /* 82944 B */

// ---------------- static scratch ----------------
__device__ float g_W[4][Rr*Cc*Cc];                           // 0:s2r 1:o2r 2:r2s 3:r2o
__device__ __align__(16) __nv_bfloat16 g_Wt_hi[4][Rr*Cc*Cc]; // transposed [n][k]
__device__ __align__(16) __nv_bfloat16 g_Wt_lo[4][Rr*Cc*Cc];
__device__ __align__(16) __nv_bfloat16 g_nf_hi[(size_t)Nn*Cc];
__device__ __align__(16) __nv_bfloat16 g_nf_lo[(size_t)Nn*Cc];
__device__ float g_v[2][Rr*Cc];
__device__ float g_scores[2][Ee];
__device__ int   g_counts[2][NK];
__device__ int   g_rowptr[2][NK+1];
__device__ int   g_cursor[2][NK];
__device__ int   g_elist[2][Ee];
__device__ int   g_partials[2][NCHUNK];
__device__ __align__(16) __nv_bfloat16 g_P_hi[(size_t)NK*Cc];
__device__ __align__(16) __nv_bfloat16 g_P_lo[(size_t)NK*Cc];
__device__ float g_invdiv[2][Nn];
__device__ int   g_binCount[2][Rr];
__device__ int   g_binStart[2][Rr+1];
__device__ int   g_tileStart[2][Rr+1];
__device__ int   g_binCursor[2][Rr];
__device__ int   g_perm[2][Ee];

// ---------------- helpers ----------------
__device__ __forceinline__ uint32_t smem_u32(const void* p){
    return (uint32_t)__cvta_generic_to_shared((void*)p);
}
__device__ __forceinline__ void cpa16(uint32_t d, const void* s){
    asm volatile("cp.async.cg.shared.global [%0], [%1], 16;" :: "r"(d), "l"(s) : "memory");
}
__device__ __forceinline__ void cpa_commit(){
    asm volatile("cp.async.commit_group;" ::: "memory");
}
__device__ __forceinline__ void cpa_wait1(){
    asm volatile("cp.async.wait_group 1;" ::: "memory");
}
__device__ __forceinline__ void cpa_wait0(){
    asm volatile("cp.async.wait_group 0;" ::: "memory");
}
__device__ __forceinline__ void mma16816(float* c, const uint32_t* a, const uint32_t* b){
    asm volatile("mma.sync.aligned.m16n8k16.row.col.f32.bf16.bf16.f32 "
        "{%0,%1,%2,%3}, {%4,%5,%6,%7}, {%8,%9}, {%0,%1,%2,%3};"
        : "+f"(c[0]), "+f"(c[1]), "+f"(c[2]), "+f"(c[3])
        : "r"(a[0]), "r"(a[1]), "r"(a[2]), "r"(a[3]), "r"(b[0]), "r"(b[1]));
}

// ---------------- setup kernels ----------------
__global__ void k_init() {
    int i = blockIdx.x*256 + threadIdx.x;
    if (i < 2*NK) ((int*)g_counts)[i] = 0;
    if (i < 2*Rr) ((int*)g_binCount)[i] = 0;
}

__global__ void k_w(const float* b0, const float* a0, const float* b1, const float* a1,
                    const float* b2, const float* a2, const float* b3, const float* a3) {
    int bx = blockIdx.x;
    int br = bx / (Rr*Cc);
    int rem = bx % (Rr*Cc);
    int r = rem / Cc, i = rem % Cc, j = threadIdx.x;
    const float* bas = (br==0)?b0:(br==1)?b1:(br==2)?b2:b3;
    const float* att = (br==0)?a0:(br==1)?a1:(br==2)?a2:a3;
    float w = 0.f;
#pragma unroll
    for (int b = 0; b < Bb; b++) w += att[r*Bb+b]*bas[(b*Cc+i)*Cc + j];
    g_W[br][(r*Cc+i)*Cc + j] = w;
}

// tiled transpose + split: g_W[br][r][i][j] -> g_Wt_hi/lo[br][r][j*256+i]
__global__ void k_wsplit() {
    __shared__ float t[32][33];
    int bid = blockIdx.x;
    int br = bid / (Rr*64);
    int rem = bid % (Rr*64);
    int r = rem / 64, tile = rem % 64;
    int ti = (tile/8)*32, tj = (tile%8)*32;
    int lx = threadIdx.x & 31, ly = threadIdx.x >> 5;
    const float* W = g_W[br] + r*Cc*Cc;
#pragma unroll
    for (int s = 0; s < 32; s += 8) t[ly+s][lx] = W[(ti+ly+s)*Cc + tj+lx];
    __syncthreads();
    __nv_bfloat16* Wh = g_Wt_hi[br] + r*Cc*Cc;
    __nv_bfloat16* Wl = g_Wt_lo[br] + r*Cc*Cc;
#pragma unroll
    for (int s = 0; s < 32; s += 8) {
        float v = t[lx][ly+s];
        __nv_bfloat16 h = __float2bfloat16(v);
        Wh[(tj+ly+s)*Cc + ti+lx] = h;
        Wl[(tj+ly+s)*Cc + ti+lx] = __float2bfloat16(v - __bfloat162float(h));
    }
}

__global__ void k_nfsplit(const float* nf) {
    int i = blockIdx.x*256 + threadIdx.x;
    float x = nf[i];
    __nv_bfloat16 h = __float2bfloat16(x);
    g_nf_hi[i] = h;
    g_nf_lo[i] = __float2bfloat16(x - __bfloat162float(h));
}

__global__ void k_v(const float* aw_sub, const float* aw_obj) {
    int br = blockIdx.x / Rr, r = blockIdx.x % Rr;
    const float* aw = (br==0) ? aw_sub : aw_obj;
    const float* W = g_W[2+br] + r*Cc*Cc;
    int i = threadIdx.x;
    float s = 0.f;
    for (int j = 0; j < Cc; j++) s += W[i*Cc+j]*aw[r*Cc+j];
    g_v[br][r*Cc+i] = s;
}

__global__ void k_hist(const int* src, const int* dst, const int* et_rel, const int* et_inv) {
    __shared__ int h[2][Rr];
    int tid = threadIdx.x;
    if (tid < 2*Rr) ((int*)h)[tid] = 0;
    __syncthreads();
#pragma unroll
    for (int u = 0; u < 4; u++) {
        int e = blockIdx.x*1024 + u*256 + tid;
        int r1 = et_rel[e], r2 = et_inv[e];
        atomicAdd(&h[0][r1], 1); atomicAdd(&h[1][r2], 1);
        atomicAdd(&g_counts[0][src[e]*Rr + r2], 1);
        atomicAdd(&g_counts[1][dst[e]*Rr + r1], 1);
    }
    __syncthreads();
    if (tid < Rr) {
        atomicAdd(&g_binCount[0][tid], h[0][tid]);
        atomicAdd(&g_binCount[1][tid], h[1][tid]);
    }
}

__global__ void k_smallscan() {
    int br = threadIdx.x;
    if (br < 2) {
        int s = 0, t = 0;
        for (int r = 0; r < Rr; r++) {
            g_binStart[br][r] = s; g_tileStart[br][r] = t; g_binCursor[br][r] = s;
            int c = g_binCount[br][r];
            s += c; t += (c + TILE_M-1)/TILE_M;
        }
        g_binStart[br][Rr] = s; g_tileStart[br][Rr] = t;
    }
}

__global__ void k_binscatter(const int* et_rel, const int* et_inv) {
    __shared__ int h[2][Rr], base[2][Rr], loc[2][Rr];
    int tid = threadIdx.x;
    if (tid < 2*Rr) { ((int*)h)[tid] = 0; ((int*)loc)[tid] = 0; }
    __syncthreads();
    int es[4], r1s[4], r2s[4];
#pragma unroll
    for (int u = 0; u < 4; u++) {
        int e = blockIdx.x*1024 + u*256 + tid;
        es[u] = e; r1s[u] = et_rel[e]; r2s[u] = et_inv[e];
        atomicAdd(&h[0][r1s[u]], 1); atomicAdd(&h[1][r2s[u]], 1);
    }
    __syncthreads();
    if (tid < Rr) {
        base[0][tid] = atomicAdd(&g_binCursor[0][tid], h[0][tid]);
        base[1][tid] = atomicAdd(&g_binCursor[1][tid], h[1][tid]);
    }
    __syncthreads();
#pragma unroll
    for (int u = 0; u < 4; u++) {
        int p0 = base[0][r1s[u]] + atomicAdd(&loc[0][r1s[u]], 1);
        g_perm[0][p0] = es[u];
        int p1 = base[1][r2s[u]] + atomicAdd(&loc[1][r2s[u]], 1);
        g_perm[1][p1] = es[u];
    }
}

__global__ void k_scan1() {
    int br = blockIdx.x / NCHUNK, ch = blockIdx.x % NCHUNK;
    int tid = threadIdx.x;
    int basei = ch*1024 + tid*4;
    int v[4]; int t = 0;
#pragma unroll
    for (int i = 0; i < 4; i++) { v[i] = g_counts[br][basei+i]; t += v[i]; }
    __shared__ int s[256];
    s[tid] = t; __syncthreads();
    for (int off = 1; off < 256; off <<= 1) {
        int x = (tid >= off) ? s[tid-off] : 0;
        __syncthreads();
        s[tid] += x;
        __syncthreads();
    }
    int excl = s[tid] - t;
#pragma unroll
    for (int i = 0; i < 4; i++) { g_rowptr[br][basei+i] = excl; excl += v[i]; }
    if (tid == 255) g_partials[br][ch] = s[255];
}

__global__ void k_scan2() {
    int br = threadIdx.x;
    if (br < 2) {
        int run = 0;
        for (int c = 0; c < NCHUNK; c++) { int p = g_partials[br][c]; g_partials[br][c] = run; run += p; }
        g_rowptr[br][NK] = run;
    }
}

__global__ void k_scan3() {
    int br = blockIdx.x / NCHUNK, ch = blockIdx.x % NCHUNK;
    int add = g_partials[br][ch];
    int basei = ch*1024 + threadIdx.x*4;
#pragma unroll
    for (int i = 0; i < 4; i++) {
        int p = g_rowptr[br][basei+i] + add;
        g_rowptr[br][basei+i] = p;
        g_cursor[br][basei+i] = p;
    }
}

__global__ void k_csrscatter(const int* src, const int* dst, const int* et_rel, const int* et_inv) {
    int e = blockIdx.x*256 + threadIdx.x;
    int k0 = src[e]*Rr + et_inv[e];
    g_elist[0][atomicAdd(&g_cursor[0][k0], 1)] = e;
    int k1 = dst[e]*Rr + et_rel[e];
    g_elist[1][atomicAdd(&g_cursor[1][k1], 1)] = e;
}

__global__ void k_invdiv() {
    int n = blockIdx.x*256 + threadIdx.x;
#pragma unroll
    for (int br = 0; br < 2; br++) {
        int c = 0;
        for (int r = 0; r < Rr; r++)
            if (g_rowptr[br][n*Rr+r+1] > g_rowptr[br][n*Rr+r]) c++;
        g_invdiv[br][n] = c ? 1.f/(float)c : 1.f;
    }
}

// ---------------- HMMA edge GEMM: rel = ef + 0.5*(nf[gather]@W) ----------------
// MODE 0: s2r (perm by et_rel, gather src, write ef + 0.5*acc)
// MODE 1: o2r (perm by et_inv, gather dst, += 0.5*acc)
template<int MODE>
__global__ void __launch_bounds__(256) k_mma_edge(const int* __restrict__ idx,
        const float* __restrict__ ef, float* __restrict__ rel_out) {
    extern __shared__ char smem[];
    int bx = blockIdx.x, cy = blockIdx.y;
    if (bx >= g_tileStart[MODE][Rr]) return;
    int r = 0;
    while (bx >= g_tileStart[MODE][r+1]) r++;
    int row0 = g_binStart[MODE][r] + (bx - g_tileStart[MODE][r])*TILE_M;
    int rowEnd = g_binStart[MODE][r+1];

    int tid = threadIdx.x;
    int* es = (int*)smem;
    int* gs = es + 128;
    if (tid < 128) {
        int row = row0 + tid;
        if (row < rowEnd) { int e = g_perm[MODE][row]; es[tid] = e; gs[tid] = idx[e]; }
        else { es[tid] = -1; gs[tid] = 0; }
    }
    __syncthreads();

    const __nv_bfloat16* Whi = g_Wt_hi[MODE] + (size_t)r*Cc*Cc + (size_t)cy*128*Cc;
    const __nv_bfloat16* Wlo = g_Wt_lo[MODE] + (size_t)r*Cc*Cc + (size_t)cy*128*Cc;

    __nv_bfloat16* pAH[2]; __nv_bfloat16* pAL[2]; __nv_bfloat16* pBH[2]; __nv_bfloat16* pBL[2];
#pragma unroll
    for (int s = 0; s < 2; s++) {
        __nv_bfloat16* b = (__nv_bfloat16*)(smem + SM_BASE) + s*4*PART_ELE;
        pAH[s] = b; pAL[s] = b + PART_ELE; pBH[s] = b + 2*PART_ELE; pBL[s] = b + 3*PART_ELE;
    }

    auto load_chunk = [&](int ch, int st){
        int k0 = ch*32;
#pragma unroll
        for (int it = 0; it < 2; it++) {
            int i = it*256 + tid; int row = i>>2, c16 = i&3;
            size_t so = (size_t)gs[row]*Cc + k0 + c16*8;
            int dof = row*PADK + c16*8;
            cpa16(smem_u32(pAH[st] + dof), g_nf_hi + so);
            cpa16(smem_u32(pAL[st] + dof), g_nf_lo + so);
        }
#pragma unroll
        for (int it = 0; it < 2; it++) {
            int i = it*256 + tid; int row = i>>2, c16 = i&3;
            size_t so = (size_t)row*Cc + k0 + c16*8;
            int dof = row*PADK + c16*8;
            cpa16(smem_u32(pBH[st] + dof), Whi + so);
            cpa16(smem_u32(pBL[st] + dof), Wlo + so);
        }
        cpa_commit();
    };

    int lane = tid & 31, wid = tid >> 5;
    int gid = lane >> 2, tig = lane & 3;
    int wm = wid & 3, wn = wid >> 2;

    float acc[2][8][4];
#pragma unroll
    for (int mt = 0; mt < 2; mt++)
#pragma unroll
        for (int nt = 0; nt < 8; nt++)
#pragma unroll
            for (int q = 0; q < 4; q++) acc[mt][nt][q] = 0.f;

    load_chunk(0, 0);
    for (int ch = 0; ch < 8; ch++) {
        if (ch < 7) { load_chunk(ch+1, (ch+1)&1); cpa_wait1(); }
        else cpa_wait0();
        __syncthreads();
        int st = ch & 1;
        const __nv_bfloat16* AH = pAH[st]; const __nv_bfloat16* AL = pAL[st];
        const __nv_bfloat16* BH = pBH[st]; const __nv_bfloat16* BL = pBL[st];
#pragma unroll
        for (int ks = 0; ks < 2; ks++) {
            int kc = ks*16 + 2*tig;
            uint32_t ah[2][4], al[2][4];
#pragma unroll
            for (int mt = 0; mt < 2; mt++) {
                int r0 = (wm*32 + mt*16 + gid)*PADK + kc;
                ah[mt][0] = *(const uint32_t*)(AH + r0);
                ah[mt][1] = *(const uint32_t*)(AH + r0 + 8*PADK);
                ah[mt][2] = *(const uint32_t*)(AH + r0 + 8);
                ah[mt][3] = *(const uint32_t*)(AH + r0 + 8*PADK + 8);
                al[mt][0] = *(const uint32_t*)(AL + r0);
                al[mt][1] = *(const uint32_t*)(AL + r0 + 8*PADK);
                al[mt][2] = *(const uint32_t*)(AL + r0 + 8);
                al[mt][3] = *(const uint32_t*)(AL + r0 + 8*PADK + 8);
            }
            uint32_t bh[8][2], bl[8][2];
#pragma unroll
            for (int nt = 0; nt < 8; nt++) {
                int nr = (wn*64 + nt*8 + gid)*PADK + kc;
                bh[nt][0] = *(const uint32_t*)(BH + nr);
                bh[nt][1] = *(const uint32_t*)(BH + nr + 8);
                bl[nt][0] = *(const uint32_t*)(BL + nr);
                bl[nt][1] = *(const uint32_t*)(BL + nr + 8);
            }
#pragma unroll
            for (int mt = 0; mt < 2; mt++)
#pragma unroll
                for (int nt = 0; nt < 8; nt++) {
                    mma16816(acc[mt][nt], ah[mt], bh[nt]);
                    mma16816(acc[mt][nt], ah[mt], bl[nt]);
                    mma16816(acc[mt][nt], al[mt], bh[nt]);
                }
        }
        __syncthreads();
    }

    int cbase = cy*128 + wn*64 + 2*tig;
#pragma unroll
    for (int mt = 0; mt < 2; mt++)
#pragma unroll
        for (int h = 0; h < 2; h++) {
            int row = wm*32 + mt*16 + h*8 + gid;
            int e = es[row];
            if (e < 0) continue;
            float* op = rel_out + (size_t)e*Cc + cbase;
            const float* efp = ef + (size_t)e*Cc + cbase;
#pragma unroll
            for (int nt = 0; nt < 8; nt++) {
                float vx = 0.5f*acc[mt][nt][h*2+0];
                float vy = 0.5f*acc[mt][nt][h*2+1];
                if (MODE == 0) {
                    float2 e2 = *(const float2*)(efp + nt*8);
                    float2 w; w.x = e2.x + vx; w.y = e2.y + vy;
                    *(float2*)(op + nt*8) = w;
                } else {
                    float2 cur = *(const float2*)(op + nt*8);
                    cur.x += vx; cur.y += vy;
                    *(float2*)(op + nt*8) = cur;
                }
            }
        }
}

// scores: leaky_relu(rel . v[r] + b[r]) for both branches (one warp/edge)
__global__ void k_score(const float* __restrict__ rel, const int* __restrict__ et_rel,
                        const int* __restrict__ et_inv,
                        const float* __restrict__ ab_sub, const float* __restrict__ ab_obj) {
    int w = (blockIdx.x*blockDim.x + threadIdx.x) >> 5;
    int lane = threadIdx.x & 31;
    if (w >= Ee) return;
    int e = w;
    int r1 = et_rel[e], r2 = et_inv[e];
    const float* x = rel + (size_t)e*Cc;
    const float* vs = g_v[0] + r2*Cc;
    const float* vo = g_v[1] + r1*Cc;
    float s0 = 0.f, s1 = 0.f;
#pragma unroll
    for (int i = 0; i < 8; i++) {
        float xv = x[i*32 + lane];
        s0 += xv*vs[i*32 + lane];
        s1 += xv*vo[i*32 + lane];
    }
#pragma unroll
    for (int o = 16; o > 0; o >>= 1) {
        s0 += __shfl_down_sync(0xffffffffu, s0, o);
        s1 += __shfl_down_sync(0xffffffffu, s1, o);
    }
    if (lane == 0) {
        float a = s0 + ab_sub[r2]; a = (a >= 0.f) ? a : 0.01f*a; g_scores[0][e] = a;
        float b = s1 + ab_obj[r1]; b = (b >= 0.f) ? b : 0.01f*b; g_scores[1][e] = b;
    }
}

// P fill: softmax-weighted sums per (node,rel) key -> bf16 hi/lo
__global__ void k_pfill(const float* __restrict__ rel, int br) {
    int w = blockIdx.x*8 + (threadIdx.x >> 5);
    int lane = threadIdx.x & 31;
    if (w >= NK) return;
    int lo = g_rowptr[br][w], hi = g_rowptr[br][w+1];
    float acc[8];
#pragma unroll
    for (int i = 0; i < 8; i++) acc[i] = 0.f;
    if (lo < hi) {
        float m = -1e30f;
        for (int p = lo; p < hi; p++) m = fmaxf(m, g_scores[br][g_elist[br][p]]);
        float den = 0.f;
        for (int p = lo; p < hi; p++) {
            int e = g_elist[br][p];
            float wt = expf(g_scores[br][e] - m);
            den += wt;
            const float* x = rel + (size_t)e*Cc;
#pragma unroll
            for (int i = 0; i < 8; i++) acc[i] += wt*x[i*32 + lane];
        }
        float inv = 1.f/den;
#pragma unroll
        for (int i = 0; i < 8; i++) acc[i] *= inv;
    }
    __nv_bfloat16* Ph = g_P_hi + (size_t)w*Cc;
    __nv_bfloat16* Pl = g_P_lo + (size_t)w*Cc;
#pragma unroll
    for (int i = 0; i < 8; i++) {
        float a = acc[i];
        __nv_bfloat16 h = __float2bfloat16(a);
        Ph[i*32+lane] = h;
        Pl[i*32+lane] = __float2bfloat16(a - __bfloat162float(h));
    }
}

// ---------------- HMMA agg GEMM: out[n] (=/+=) nf + 0.5*invdiv*P[n,:]@Wcat ----------------
template<int BR>
__global__ void __launch_bounds__(256) k_mma_g3(const float* __restrict__ nf,
                                                float* __restrict__ node_out) {
    extern __shared__ char smem[];
    int n0 = blockIdx.x*TILE_M, cy = blockIdx.y;
    int tid = threadIdx.x;

    __nv_bfloat16* pAH[2]; __nv_bfloat16* pAL[2]; __nv_bfloat16* pBH[2]; __nv_bfloat16* pBL[2];
#pragma unroll
    for (int s = 0; s < 2; s++) {
        __nv_bfloat16* b = (__nv_bfloat16*)(smem + SM_BASE) + s*4*PART_ELE;
        pAH[s] = b; pAL[s] = b + PART_ELE; pBH[s] = b + 2*PART_ELE; pBL[s] = b + 3*PART_ELE;
    }
    const __nv_bfloat16* Phi = g_P_hi + (size_t)n0*(Rr*Cc);
    const __nv_bfloat16* Plo = g_P_lo + (size_t)n0*(Rr*Cc);

    auto load_chunk = [&](int ch, int st){
        int kk = ch*32;
#pragma unroll
        for (int it = 0; it < 2; it++) {
            int i = it*256 + tid; int row = i>>2, c16 = i&3;
            size_t so = (size_t)row*(Rr*Cc) + kk + c16*8;
            int dof = row*PADK + c16*8;
            cpa16(smem_u32(pAH[st] + dof), Phi + so);
            cpa16(smem_u32(pAL[st] + dof), Plo + so);
        }
        int rb = kk >> 8, c0 = kk & 255;
        const __nv_bfloat16* Whi = g_Wt_hi[2+BR] + (size_t)rb*Cc*Cc + (size_t)cy*128*Cc + c0;
        const __nv_bfloat16* Wlo = g_Wt_lo[2+BR] + (size_t)rb*Cc*Cc + (size_t)cy*128*Cc + c0;
#pragma unroll
        for (int it = 0; it < 2; it++) {
            int i = it*256 + tid; int row = i>>2, c16 = i&3;
            size_t so = (size_t)row*Cc + c16*8;
            int dof = row*PADK + c16*8;
            cpa16(smem_u32(pBH[st] + dof), Whi + so);
            cpa16(smem_u32(pBL[st] + dof), Wlo + so);
        }
        cpa_commit();
    };

    int lane = tid & 31, wid = tid >> 5;
    int gid = lane >> 2, tig = lane & 3;
    int wm = wid & 3, wn = wid >> 2;

    float acc[2][8][4];
#pragma unroll
    for (int mt = 0; mt < 2; mt++)
#pragma unroll
        for (int nt = 0; nt < 8; nt++)
#pragma unroll
            for (int q = 0; q < 4; q++) acc[mt][nt][q] = 0.f;

    const int NCH = (Rr*Cc)/32;   /* 72 */
    load_chunk(0, 0);
    for (int ch = 0; ch < NCH; ch++) {
        if (ch < NCH-1) { load_chunk(ch+1, (ch+1)&1); cpa_wait1(); }
        else cpa_wait0();
        __syncthreads();
        int st = ch & 1;
        const __nv_bfloat16* AH = pAH[st]; const __nv_bfloat16* AL = pAL[st];
        const __nv_bfloat16* BH = pBH[st]; const __nv_bfloat16* BL = pBL[st];
#pragma unroll
        for (int ks = 0; ks < 2; ks++) {
            int kc = ks*16 + 2*tig;
            uint32_t ah[2][4], al[2][4];
#pragma unroll
            for (int mt = 0; mt < 2; mt++) {
                int r0 = (wm*32 + mt*16 + gid)*PADK + kc;
                ah[mt][0] = *(const uint32_t*)(AH + r0);
                ah[mt][1] = *(const uint32_t*)(AH + r0 + 8*PADK);
                ah[mt][2] = *(const uint32_t*)(AH + r0 + 8);
                ah[mt][3] = *(const uint32_t*)(AH + r0 + 8*PADK + 8);
                al[mt][0] = *(const uint32_t*)(AL + r0);
                al[mt][1] = *(const uint32_t*)(AL + r0 + 8*PADK);
                al[mt][2] = *(const uint32_t*)(AL + r0 + 8);
                al[mt][3] = *(const uint32_t*)(AL + r0 + 8*PADK + 8);
            }
            uint32_t bh[8][2], bl[8][2];
#pragma unroll
            for (int nt = 0; nt < 8; nt++) {
                int nr = (wn*64 + nt*8 + gid)*PADK + kc;
                bh[nt][0] = *(const uint32_t*)(BH + nr);
                bh[nt][1] = *(const uint32_t*)(BH + nr + 8);
                bl[nt][0] = *(const uint32_t*)(BL + nr);
                bl[nt][1] = *(const uint32_t*)(BL + nr + 8);
            }
#pragma unroll
            for (int mt = 0; mt < 2; mt++)
#pragma unroll
                for (int nt = 0; nt < 8; nt++) {
                    mma16816(acc[mt][nt], ah[mt], bh[nt]);
                    mma16816(acc[mt][nt], ah[mt], bl[nt]);
                    mma16816(acc[mt][nt], al[mt], bh[nt]);
                }
        }
        __syncthreads();
    }

    int cbase = cy*128 + wn*64 + 2*tig;
#pragma unroll
    for (int mt = 0; mt < 2; mt++)
#pragma unroll
        for (int h = 0; h < 2; h++) {
            int n = n0 + wm*32 + mt*16 + h*8 + gid;
            float sc = 0.5f*g_invdiv[BR][n];
            float* op = node_out + (size_t)n*Cc + cbase;
            const float* nfp = nf + (size_t)n*Cc + cbase;
#pragma unroll
            for (int nt = 0; nt < 8; nt++) {
                float vx = sc*acc[mt][nt][h*2+0];
                float vy = sc*acc[mt][nt][h*2+1];
                if (BR == 0) {
                    float2 b2 = *(const float2*)(nfp + nt*8);
                    float2 w; w.x = b2.x + vx; w.y = b2.y + vy;
                    *(float2*)(op + nt*8) = w;
                } else {
                    float2 cur = *(const float2*)(op + nt*8);
                    cur.x += vx; cur.y += vy;
                    *(float2*)(op + nt*8) = cur;
                }
            }
        }
}

extern "C" void kernel_launch(void* const* d_in, const int* in_sizes, int n_in,
                              void* d_out, int out_size) {
    const int* ei      = (const int*)d_in[0];
    const int* src     = ei;
    const int* dst     = ei + Ee;
    const float* nf    = (const float*)d_in[1];
    const float* ef    = (const float*)d_in[2];
    const int* et_rel  = (const int*)d_in[3];
    const int* et_inv  = (const int*)d_in[4];
    const float* s2r_b = (const float*)d_in[6];
    const float* s2r_a = (const float*)d_in[7];
    const float* o2r_b = (const float*)d_in[8];
    const float* o2r_a = (const float*)d_in[9];
    const float* r2s_b = (const float*)d_in[10];
    const float* r2s_a = (const float*)d_in[11];
    const float* r2s_w = (const float*)d_in[12];
    const float* r2s_bias = (const float*)d_in[13];
    const float* r2o_b = (const float*)d_in[14];
    const float* r2o_a = (const float*)d_in[15];
    const float* r2o_w = (const float*)d_in[16];
    const float* r2o_bias = (const float*)d_in[17];

    float* node_out = (float*)d_out;
    float* rel_out  = node_out + (size_t)Nn*Cc;

    cudaFuncSetAttribute(k_mma_edge<0>, cudaFuncAttributeMaxDynamicSharedMemorySize, SM_TOTAL);
    cudaFuncSetAttribute(k_mma_edge<1>, cudaFuncAttributeMaxDynamicSharedMemorySize, SM_TOTAL);
    cudaFuncSetAttribute(k_mma_g3<0>, cudaFuncAttributeMaxDynamicSharedMemorySize, SM_TOTAL);
    cudaFuncSetAttribute(k_mma_g3<1>, cudaFuncAttributeMaxDynamicSharedMemorySize, SM_TOTAL);

    k_init<<<(2*NK + 255)/256, 256>>>();
    k_w<<<4*Rr*Cc, 256>>>(s2r_b, s2r_a, o2r_b, o2r_a, r2s_b, r2s_a, r2o_b, r2o_a);
    k_wsplit<<<4*Rr*64, 256>>>();
    k_nfsplit<<<(Nn*Cc)/256, 256>>>(nf);
    k_v<<<2*Rr, 256>>>(r2s_w, r2o_w);
    k_hist<<<256, 256>>>(src, dst, et_rel, et_inv);
    k_smallscan<<<1, 32>>>();
    k_binscatter<<<256, 256>>>(et_rel, et_inv);
    k_scan1<<<2*NCHUNK, 256>>>();
    k_scan2<<<1, 32>>>();
    k_scan3<<<2*NCHUNK, 256>>>();
    k_csrscatter<<<Ee/256, 256>>>(src, dst, et_rel, et_inv);
    k_invdiv<<<Nn/256, 256>>>();

    dim3 ge(MAXTILES, 2);
    k_mma_edge<0><<<ge, 256, SM_TOTAL>>>(src, ef, rel_out);
    k_mma_edge<1><<<ge, 256, SM_TOTAL>>>(dst, ef, rel_out);

    k_score<<<Ee/8, 256>>>(rel_out, et_rel, et_inv, r2s_bias, r2o_bias);

    dim3 g3(Nn/TILE_M, 2);
    k_pfill<<<NK/8, 256>>>(rel_out, 0);
    k_mma_g3<0><<<g3, 256, SM_TOTAL>>>(nf, node_out);
    k_pfill<<<NK/8, 256>>>(rel_out, 1);
    k_mma_g3<1><<<g3, 256, SM_TOTAL>>>(nf, node_out);
}

// round 7
// speedup vs baseline: 2.2059x; 1.0699x over previous
#include <cuda_runtime.h>
#include <cuda_bf16.h>
#include <math.h>
#include <stdint.h>

#define Nn 16384
#define Ee 262144
#define Cc 256
#define Rr 9
#define Bb 4
#define NK (Nn*Rr)
#define NCHUNK (NK/1024)
#define TILE_M 128
#define NPAIR (Rr*Rr)                 /* 81 */
#define TILES2 (Ee/TILE_M + NPAIR)    /* 2129 */

#define PADK 40                       /* padded bf16 cols per 32-col chunk row */

/* edge kernel smem */
#define SM2_ES   0
#define SM2_GSS  512
#define SM2_GSD  1024
#define SM2_BUF  2048
#define A_BYTES  (128*PADK*2)         /* 10240 */
#define B_BYTES  (256*PADK*2)         /* 20480 */
#define SSTRIDE  (2*A_BYTES + 2*B_BYTES)  /* 61440 */
#define SM2_TOTAL (SM2_BUF + 2*SSTRIDE)   /* 124928 */
#define SM3_TOTAL (2*SSTRIDE)             /* 122880 */

// ---------------- static scratch ----------------
__device__ float g_W[4][Rr*Cc*Cc];                           // 0:s2r 1:o2r 2:r2s 3:r2o
__device__ __align__(16) __nv_bfloat16 g_Wt_hi[4][Rr*Cc*Cc]; // transposed [n][k]
__device__ __align__(16) __nv_bfloat16 g_Wt_lo[4][Rr*Cc*Cc];
__device__ __align__(16) __nv_bfloat16 g_nf_hi[(size_t)Nn*Cc];
__device__ __align__(16) __nv_bfloat16 g_nf_lo[(size_t)Nn*Cc];
__device__ float g_v[2][Rr*Cc];
__device__ float g_scores[2][Ee];
__device__ int   g_counts[2][NK];
__device__ int   g_rowptr[2][NK+1];
__device__ int   g_cursor[2][NK];
__device__ int   g_elist[2][Ee];
__device__ int   g_partials[2][NCHUNK];
__device__ __align__(16) __nv_bfloat16 g_Ph[2][(size_t)NK*Cc];
__device__ __align__(16) __nv_bfloat16 g_Pl[2][(size_t)NK*Cc];
__device__ float g_invdiv[2][Nn];
__device__ int   g_pairCount[NPAIR];
__device__ int   g_pairStart[NPAIR+1];
__device__ int   g_tileStart2[NPAIR+1];
__device__ int   g_pairCursor[NPAIR];
__device__ int   g_perm2[Ee];

// ---------------- helpers ----------------
__device__ __forceinline__ uint32_t smem_u32(const void* p){
    return (uint32_t)__cvta_generic_to_shared((void*)p);
}
__device__ __forceinline__ void cpa16(uint32_t d, const void* s){
    asm volatile("cp.async.cg.shared.global [%0], [%1], 16;" :: "r"(d), "l"(s) : "memory");
}
__device__ __forceinline__ void cpa_commit(){
    asm volatile("cp.async.commit_group;" ::: "memory");
}
__device__ __forceinline__ void cpa_wait1(){
    asm volatile("cp.async.wait_group 1;" ::: "memory");
}
__device__ __forceinline__ void cpa_wait0(){
    asm volatile("cp.async.wait_group 0;" ::: "memory");
}
__device__ __forceinline__ void mma16816(float* c, const uint32_t* a, uint32_t b0, uint32_t b1){
    asm volatile("mma.sync.aligned.m16n8k16.row.col.f32.bf16.bf16.f32 "
        "{%0,%1,%2,%3}, {%4,%5,%6,%7}, {%8,%9}, {%0,%1,%2,%3};"
        : "+f"(c[0]), "+f"(c[1]), "+f"(c[2]), "+f"(c[3])
        : "r"(a[0]), "r"(a[1]), "r"(a[2]), "r"(a[3]), "r"(b0), "r"(b1));
}

// ---------------- setup kernels ----------------
__global__ void k_init() {
    int i = blockIdx.x*256 + threadIdx.x;
    if (i < 2*NK) ((int*)g_counts)[i] = 0;
    if (i < NPAIR) g_pairCount[i] = 0;
}

__global__ void k_w(const float* b0, const float* a0, const float* b1, const float* a1,
                    const float* b2, const float* a2, const float* b3, const float* a3) {
    int bx = blockIdx.x;
    int br = bx / (Rr*Cc);
    int rem = bx % (Rr*Cc);
    int r = rem / Cc, i = rem % Cc, j = threadIdx.x;
    const float* bas = (br==0)?b0:(br==1)?b1:(br==2)?b2:b3;
    const float* att = (br==0)?a0:(br==1)?a1:(br==2)?a2:a3;
    float w = 0.f;
#pragma unroll
    for (int b = 0; b < Bb; b++) w += att[r*Bb+b]*bas[(b*Cc+i)*Cc + j];
    g_W[br][(r*Cc+i)*Cc + j] = w;
}

// tiled transpose + split: g_W[br][r][i][j] -> g_Wt_hi/lo[br][r][j*256+i]
__global__ void k_wsplit() {
    __shared__ float t[32][33];
    int bid = blockIdx.x;
    int br = bid / (Rr*64);
    int rem = bid % (Rr*64);
    int r = rem / 64, tile = rem % 64;
    int ti = (tile/8)*32, tj = (tile%8)*32;
    int lx = threadIdx.x & 31, ly = threadIdx.x >> 5;
    const float* W = g_W[br] + r*Cc*Cc;
#pragma unroll
    for (int s = 0; s < 32; s += 8) t[ly+s][lx] = W[(ti+ly+s)*Cc + tj+lx];
    __syncthreads();
    __nv_bfloat16* Wh = g_Wt_hi[br] + r*Cc*Cc;
    __nv_bfloat16* Wl = g_Wt_lo[br] + r*Cc*Cc;
#pragma unroll
    for (int s = 0; s < 32; s += 8) {
        float v = t[lx][ly+s];
        __nv_bfloat16 h = __float2bfloat16(v);
        Wh[(tj+ly+s)*Cc + ti+lx] = h;
        Wl[(tj+ly+s)*Cc + ti+lx] = __float2bfloat16(v - __bfloat162float(h));
    }
}

__global__ void k_nfsplit(const float* nf) {
    int i = blockIdx.x*256 + threadIdx.x;
    float x = nf[i];
    __nv_bfloat16 h = __float2bfloat16(x);
    g_nf_hi[i] = h;
    g_nf_lo[i] = __float2bfloat16(x - __bfloat162float(h));
}

__global__ void k_v(const float* aw_sub, const float* aw_obj) {
    int br = blockIdx.x / Rr, r = blockIdx.x % Rr;
    const float* aw = (br==0) ? aw_sub : aw_obj;
    const float* W = g_W[2+br] + r*Cc*Cc;
    int i = threadIdx.x;
    float s = 0.f;
    for (int j = 0; j < Cc; j++) s += W[i*Cc+j]*aw[r*Cc+j];
    g_v[br][r*Cc+i] = s;
}

// pair hist + per-(node,rel) key counts
__global__ void k_hist(const int* src, const int* dst, const int* et_rel, const int* et_inv) {
    __shared__ int h[NPAIR];
    int tid = threadIdx.x;
    if (tid < NPAIR) h[tid] = 0;
    __syncthreads();
#pragma unroll
    for (int u = 0; u < 4; u++) {
        int e = blockIdx.x*1024 + u*256 + tid;
        int r1 = et_rel[e], r2 = et_inv[e];
        atomicAdd(&h[r1*Rr + r2], 1);
        atomicAdd(&g_counts[0][src[e]*Rr + r2], 1);
        atomicAdd(&g_counts[1][dst[e]*Rr + r1], 1);
    }
    __syncthreads();
    if (tid < NPAIR) atomicAdd(&g_pairCount[tid], h[tid]);
}

__global__ void k_smallscan() {
    if (threadIdx.x == 0) {
        int s = 0, t = 0;
        for (int p = 0; p < NPAIR; p++) {
            g_pairStart[p] = s; g_tileStart2[p] = t; g_pairCursor[p] = s;
            int c = g_pairCount[p];
            s += c; t += (c + TILE_M-1)/TILE_M;
        }
        g_pairStart[NPAIR] = s; g_tileStart2[NPAIR] = t;
    }
}

__global__ void k_binscatter(const int* et_rel, const int* et_inv) {
    __shared__ int h[NPAIR], base[NPAIR], loc[NPAIR];
    int tid = threadIdx.x;
    if (tid < NPAIR) { h[tid] = 0; loc[tid] = 0; }
    __syncthreads();
    int es[4], ps[4];
#pragma unroll
    for (int u = 0; u < 4; u++) {
        int e = blockIdx.x*1024 + u*256 + tid;
        es[u] = e; ps[u] = et_rel[e]*Rr + et_inv[e];
        atomicAdd(&h[ps[u]], 1);
    }
    __syncthreads();
    if (tid < NPAIR) base[tid] = atomicAdd(&g_pairCursor[tid], h[tid]);
    __syncthreads();
#pragma unroll
    for (int u = 0; u < 4; u++) {
        int p = base[ps[u]] + atomicAdd(&loc[ps[u]], 1);
        g_perm2[p] = es[u];
    }
}

__global__ void k_scan1() {
    int br = blockIdx.x / NCHUNK, ch = blockIdx.x % NCHUNK;
    int tid = threadIdx.x;
    int basei = ch*1024 + tid*4;
    int v[4]; int t = 0;
#pragma unroll
    for (int i = 0; i < 4; i++) { v[i] = g_counts[br][basei+i]; t += v[i]; }
    __shared__ int s[256];
    s[tid] = t; __syncthreads();
    for (int off = 1; off < 256; off <<= 1) {
        int x = (tid >= off) ? s[tid-off] : 0;
        __syncthreads();
        s[tid] += x;
        __syncthreads();
    }
    int excl = s[tid] - t;
#pragma unroll
    for (int i = 0; i < 4; i++) { g_rowptr[br][basei+i] = excl; excl += v[i]; }
    if (tid == 255) g_partials[br][ch] = s[255];
}

__global__ void k_scan2() {
    int br = threadIdx.x;
    if (br < 2) {
        int run = 0;
        for (int c = 0; c < NCHUNK; c++) { int p = g_partials[br][c]; g_partials[br][c] = run; run += p; }
        g_rowptr[br][NK] = run;
    }
}

__global__ void k_scan3() {
    int br = blockIdx.x / NCHUNK, ch = blockIdx.x % NCHUNK;
    int add = g_partials[br][ch];
    int basei = ch*1024 + threadIdx.x*4;
#pragma unroll
    for (int i = 0; i < 4; i++) {
        int p = g_rowptr[br][basei+i] + add;
        g_rowptr[br][basei+i] = p;
        g_cursor[br][basei+i] = p;
    }
}

__global__ void k_csrscatter(const int* src, const int* dst, const int* et_rel, const int* et_inv) {
    int e = blockIdx.x*256 + threadIdx.x;
    int k0 = src[e]*Rr + et_inv[e];
    g_elist[0][atomicAdd(&g_cursor[0][k0], 1)] = e;
    int k1 = dst[e]*Rr + et_rel[e];
    g_elist[1][atomicAdd(&g_cursor[1][k1], 1)] = e;
}

__global__ void k_invdiv() {
    int n = blockIdx.x*256 + threadIdx.x;
#pragma unroll
    for (int br = 0; br < 2; br++) {
        int c = 0;
        for (int r = 0; r < Rr; r++)
            if (g_rowptr[br][n*Rr+r+1] > g_rowptr[br][n*Rr+r]) c++;
        g_invdiv[br][n] = c ? 1.f/(float)c : 1.f;
    }
}

// ---------------- fused pair-binned edge GEMM + score ----------------
// rel = ef + 0.5*([nf[src],nf[dst]] @ [W0[r1];W1[r2]])  (K=512), fused leaky-relu scores
__global__ void __launch_bounds__(512,1) k_edge(const int* __restrict__ src,
        const int* __restrict__ dst, const float* __restrict__ ef,
        float* __restrict__ rel_out,
        const float* __restrict__ bias_sub, const float* __restrict__ bias_obj) {
    extern __shared__ char smem[];
    int bx = blockIdx.x;
    if (bx >= g_tileStart2[NPAIR]) return;
    int pr = 0;
    while (bx >= g_tileStart2[pr+1]) pr++;
    int r1 = pr / Rr, r2 = pr % Rr;
    int row0 = g_pairStart[pr] + (bx - g_tileStart2[pr])*TILE_M;
    int rowEnd = g_pairStart[pr+1];

    int tid = threadIdx.x;
    int* es  = (int*)(smem + SM2_ES);
    int* gsS = (int*)(smem + SM2_GSS);
    int* gsD = (int*)(smem + SM2_GSD);
    if (tid < 128) {
        int row = row0 + tid;
        if (row < rowEnd) { int e = g_perm2[row]; es[tid] = e; gsS[tid] = src[e]; gsD[tid] = dst[e]; }
        else { es[tid] = -1; gsS[tid] = 0; gsD[tid] = 0; }
    }
    __syncthreads();

    const __nv_bfloat16* W1h = g_Wt_hi[0] + (size_t)r1*Cc*Cc;
    const __nv_bfloat16* W1l = g_Wt_lo[0] + (size_t)r1*Cc*Cc;
    const __nv_bfloat16* W2h = g_Wt_hi[1] + (size_t)r2*Cc*Cc;
    const __nv_bfloat16* W2l = g_Wt_lo[1] + (size_t)r2*Cc*Cc;

    auto load_chunk = [&](int ch, int st){
        char* base = smem + SM2_BUF + st*SSTRIDE;
        __nv_bfloat16* AH = (__nv_bfloat16*)base;
        __nv_bfloat16* AL = (__nv_bfloat16*)(base + A_BYTES);
        __nv_bfloat16* BH = (__nv_bfloat16*)(base + 2*A_BYTES);
        __nv_bfloat16* BL = (__nv_bfloat16*)(base + 2*A_BYTES + B_BYTES);
        int srcside = ch < 8;
        int k0 = (ch & 7)*32;
        {
            int row = tid >> 2, c16 = tid & 3;
            int node = srcside ? gsS[row] : gsD[row];
            size_t so = (size_t)node*Cc + k0 + c16*8;
            int dof = row*PADK + c16*8;
            cpa16(smem_u32(AH + dof), g_nf_hi + so);
            cpa16(smem_u32(AL + dof), g_nf_lo + so);
        }
        const __nv_bfloat16* Wh = srcside ? W1h : W2h;
        const __nv_bfloat16* Wl = srcside ? W1l : W2l;
#pragma unroll
        for (int it = 0; it < 2; it++) {
            int i = it*512 + tid; int row = i >> 2, c16 = i & 3;
            size_t so = (size_t)row*Cc + k0 + c16*8;
            int dof = row*PADK + c16*8;
            cpa16(smem_u32(BH + dof), Wh + so);
            cpa16(smem_u32(BL + dof), Wl + so);
        }
        cpa_commit();
    };

    int lane = tid & 31, wid = tid >> 5;
    int gid = lane >> 2, tig = lane & 3;
    int wm = wid & 3, wn = wid >> 2;

    float acc[2][8][4];
#pragma unroll
    for (int mt = 0; mt < 2; mt++)
#pragma unroll
        for (int nt = 0; nt < 8; nt++)
#pragma unroll
            for (int q = 0; q < 4; q++) acc[mt][nt][q] = 0.f;

    load_chunk(0, 0);
    for (int ch = 0; ch < 16; ch++) {
        if (ch < 15) { load_chunk(ch+1, (ch+1)&1); cpa_wait1(); }
        else cpa_wait0();
        __syncthreads();
        char* base = smem + SM2_BUF + (ch&1)*SSTRIDE;
        const __nv_bfloat16* AH = (const __nv_bfloat16*)base;
        const __nv_bfloat16* AL = (const __nv_bfloat16*)(base + A_BYTES);
        const __nv_bfloat16* BH = (const __nv_bfloat16*)(base + 2*A_BYTES);
        const __nv_bfloat16* BL = (const __nv_bfloat16*)(base + 2*A_BYTES + B_BYTES);
#pragma unroll
        for (int ks = 0; ks < 2; ks++) {
            int kc = ks*16 + 2*tig;
            uint32_t ah[2][4], al[2][4];
#pragma unroll
            for (int mt = 0; mt < 2; mt++) {
                int r0 = (wm*32 + mt*16 + gid)*PADK + kc;
                ah[mt][0] = *(const uint32_t*)(AH + r0);
                ah[mt][1] = *(const uint32_t*)(AH + r0 + 8*PADK);
                ah[mt][2] = *(const uint32_t*)(AH + r0 + 8);
                ah[mt][3] = *(const uint32_t*)(AH + r0 + 8*PADK + 8);
                al[mt][0] = *(const uint32_t*)(AL + r0);
                al[mt][1] = *(const uint32_t*)(AL + r0 + 8*PADK);
                al[mt][2] = *(const uint32_t*)(AL + r0 + 8);
                al[mt][3] = *(const uint32_t*)(AL + r0 + 8*PADK + 8);
            }
#pragma unroll
            for (int nt = 0; nt < 8; nt++) {
                int nr = (wn*64 + nt*8 + gid)*PADK + kc;
                uint32_t b0h = *(const uint32_t*)(BH + nr);
                uint32_t b1h = *(const uint32_t*)(BH + nr + 8);
                uint32_t b0l = *(const uint32_t*)(BL + nr);
                uint32_t b1l = *(const uint32_t*)(BL + nr + 8);
#pragma unroll
                for (int mt = 0; mt < 2; mt++) {
                    mma16816(acc[mt][nt], ah[mt], b0h, b1h);
                    mma16816(acc[mt][nt], ah[mt], b0l, b1l);
                    mma16816(acc[mt][nt], al[mt], b0h, b1h);
                }
            }
        }
        __syncthreads();
    }

    // epilogue: rel write + fused scores
    float* sc0 = (float*)(smem + SM2_BUF);
    float* sc1 = sc0 + 128;
    if (tid < 128) { sc0[tid] = 0.f; sc1[tid] = 0.f; }
    __syncthreads();

    const float* vs = g_v[0] + r2*Cc;
    const float* vo = g_v[1] + r1*Cc;
    int cbase = wn*64 + 2*tig;
#pragma unroll
    for (int mt = 0; mt < 2; mt++)
#pragma unroll
        for (int h = 0; h < 2; h++) {
            int row = wm*32 + mt*16 + h*8 + gid;
            int e = es[row];
            float s0 = 0.f, s1 = 0.f;
            if (e >= 0) {
                float* op = rel_out + (size_t)e*Cc + cbase;
                const float* efp = ef + (size_t)e*Cc + cbase;
#pragma unroll
                for (int nt = 0; nt < 8; nt++) {
                    int c = cbase + nt*8;
                    float2 e2 = *(const float2*)(efp + nt*8);
                    float wx = e2.x + 0.5f*acc[mt][nt][h*2+0];
                    float wy = e2.y + 0.5f*acc[mt][nt][h*2+1];
                    *(float2*)(op + nt*8) = make_float2(wx, wy);
                    s0 += wx*vs[c] + wy*vs[c+1];
                    s1 += wx*vo[c] + wy*vo[c+1];
                }
            }
            s0 += __shfl_xor_sync(0xffffffffu, s0, 1);
            s0 += __shfl_xor_sync(0xffffffffu, s0, 2);
            s1 += __shfl_xor_sync(0xffffffffu, s1, 1);
            s1 += __shfl_xor_sync(0xffffffffu, s1, 2);
            if (tig == 0 && e >= 0) {
                atomicAdd(&sc0[row], s0);
                atomicAdd(&sc1[row], s1);
            }
        }
    __syncthreads();
    if (tid < 128) {
        int e = es[tid];
        if (e >= 0) {
            float a = sc0[tid] + bias_sub[r2]; a = (a >= 0.f) ? a : 0.01f*a;
            float b = sc1[tid] + bias_obj[r1]; b = (b >= 0.f) ? b : 0.01f*b;
            g_scores[0][e] = a;
            g_scores[1][e] = b;
        }
    }
}

// P fill (both branches): invdiv-scaled softmax-weighted sums -> bf16 hi/lo
__global__ void k_pfill(const float* __restrict__ rel) {
    int w = blockIdx.x*8 + (threadIdx.x >> 5);
    int lane = threadIdx.x & 31;
    int br = (w >= NK) ? 1 : 0;
    int key = w - br*NK;
    if (w >= 2*NK) return;
    int lo = g_rowptr[br][key], hi = g_rowptr[br][key+1];
    float acc[8];
#pragma unroll
    for (int i = 0; i < 8; i++) acc[i] = 0.f;
    if (lo < hi) {
        float m = -1e30f;
        for (int p = lo; p < hi; p++) m = fmaxf(m, g_scores[br][g_elist[br][p]]);
        float den = 0.f;
        for (int p = lo; p < hi; p++) {
            int e = g_elist[br][p];
            float wt = expf(g_scores[br][e] - m);
            den += wt;
            const float* x = rel + (size_t)e*Cc;
#pragma unroll
            for (int i = 0; i < 8; i++) acc[i] += wt*x[i*32 + lane];
        }
        float inv = g_invdiv[br][key/Rr]/den;
#pragma unroll
        for (int i = 0; i < 8; i++) acc[i] *= inv;
    }
    __nv_bfloat16* Ph = g_Ph[br] + (size_t)key*Cc;
    __nv_bfloat16* Pl = g_Pl[br] + (size_t)key*Cc;
#pragma unroll
    for (int i = 0; i < 8; i++) {
        float a = acc[i];
        __nv_bfloat16 h = __float2bfloat16(a);
        Ph[i*32+lane] = h;
        Pl[i*32+lane] = __float2bfloat16(a - __bfloat162float(h));
    }
}

// ---------------- fused agg GEMM: out = nf + 0.5*([P0,P1] @ [W2;W3])  (K=4608) ----------------
__global__ void __launch_bounds__(512,1) k_g3(const float* __restrict__ nf,
                                              float* __restrict__ node_out) {
    extern __shared__ char smem[];
    int n0 = blockIdx.x*TILE_M;
    int tid = threadIdx.x;

    auto load_chunk = [&](int ch, int st){
        char* base = smem + st*SSTRIDE;
        __nv_bfloat16* AH = (__nv_bfloat16*)base;
        __nv_bfloat16* AL = (__nv_bfloat16*)(base + A_BYTES);
        __nv_bfloat16* BH = (__nv_bfloat16*)(base + 2*A_BYTES);
        __nv_bfloat16* BL = (__nv_bfloat16*)(base + 2*A_BYTES + B_BYTES);
        int brs = ch >= 72;
        int kk = (brs ? ch-72 : ch)*32;
        {
            int row = tid >> 2, c16 = tid & 3;
            size_t so = (size_t)(n0+row)*(Rr*Cc) + kk + c16*8;
            int dof = row*PADK + c16*8;
            cpa16(smem_u32(AH + dof), g_Ph[brs] + so);
            cpa16(smem_u32(AL + dof), g_Pl[brs] + so);
        }
        int rb = kk >> 8, c0 = kk & 255;
        const __nv_bfloat16* Wh = g_Wt_hi[2+brs] + (size_t)rb*Cc*Cc + c0;
        const __nv_bfloat16* Wl = g_Wt_lo[2+brs] + (size_t)rb*Cc*Cc + c0;
#pragma unroll
        for (int it = 0; it < 2; it++) {
            int i = it*512 + tid; int row = i >> 2, c16 = i & 3;
            size_t so = (size_t)row*Cc + c16*8;
            int dof = row*PADK + c16*8;
            cpa16(smem_u32(BH + dof), Wh + so);
            cpa16(smem_u32(BL + dof), Wl + so);
        }
        cpa_commit();
    };

    int lane = tid & 31, wid = tid >> 5;
    int gid = lane >> 2, tig = lane & 3;
    int wm = wid & 3, wn = wid >> 2;

    float acc[2][8][4];
#pragma unroll
    for (int mt = 0; mt < 2; mt++)
#pragma unroll
        for (int nt = 0; nt < 8; nt++)
#pragma unroll
            for (int q = 0; q < 4; q++) acc[mt][nt][q] = 0.f;

    const int NCH = 144;
    load_chunk(0, 0);
    for (int ch = 0; ch < NCH; ch++) {
        if (ch < NCH-1) { load_chunk(ch+1, (ch+1)&1); cpa_wait1(); }
        else cpa_wait0();
        __syncthreads();
        char* base = smem + (ch&1)*SSTRIDE;
        const __nv_bfloat16* AH = (const __nv_bfloat16*)base;
        const __nv_bfloat16* AL = (const __nv_bfloat16*)(base + A_BYTES);
        const __nv_bfloat16* BH = (const __nv_bfloat16*)(base + 2*A_BYTES);
        const __nv_bfloat16* BL = (const __nv_bfloat16*)(base + 2*A_BYTES + B_BYTES);
#pragma unroll
        for (int ks = 0; ks < 2; ks++) {
            int kc = ks*16 + 2*tig;
            uint32_t ah[2][4], al[2][4];
#pragma unroll
            for (int mt = 0; mt < 2; mt++) {
                int r0 = (wm*32 + mt*16 + gid)*PADK + kc;
                ah[mt][0] = *(const uint32_t*)(AH + r0);
                ah[mt][1] = *(const uint32_t*)(AH + r0 + 8*PADK);
                ah[mt][2] = *(const uint32_t*)(AH + r0 + 8);
                ah[mt][3] = *(const uint32_t*)(AH + r0 + 8*PADK + 8);
                al[mt][0] = *(const uint32_t*)(AL + r0);
                al[mt][1] = *(const uint32_t*)(AL + r0 + 8*PADK);
                al[mt][2] = *(const uint32_t*)(AL + r0 + 8);
                al[mt][3] = *(const uint32_t*)(AL + r0 + 8*PADK + 8);
            }
#pragma unroll
            for (int nt = 0; nt < 8; nt++) {
                int nr = (wn*64 + nt*8 + gid)*PADK + kc;
                uint32_t b0h = *(const uint32_t*)(BH + nr);
                uint32_t b1h = *(const uint32_t*)(BH + nr + 8);
                uint32_t b0l = *(const uint32_t*)(BL + nr);
                uint32_t b1l = *(const uint32_t*)(BL + nr + 8);
#pragma unroll
                for (int mt = 0; mt < 2; mt++) {
                    mma16816(acc[mt][nt], ah[mt], b0h, b1h);
                    mma16816(acc[mt][nt], ah[mt], b0l, b1l);
                    mma16816(acc[mt][nt], al[mt], b0h, b1h);
                }
            }
        }
        __syncthreads();
    }

    int cbase = wn*64 + 2*tig;
#pragma unroll
    for (int mt = 0; mt < 2; mt++)
#pragma unroll
        for (int h = 0; h < 2; h++) {
            int n = n0 + wm*32 + mt*16 + h*8 + gid;
            float* op = node_out + (size_t)n*Cc + cbase;
            const float* nfp = nf + (size_t)n*Cc + cbase;
#pragma unroll
            for (int nt = 0; nt < 8; nt++) {
                float2 b2 = *(const float2*)(nfp + nt*8);
                float2 w;
                w.x = b2.x + 0.5f*acc[mt][nt][h*2+0];
                w.y = b2.y + 0.5f*acc[mt][nt][h*2+1];
                *(float2*)(op + nt*8) = w;
            }
        }
}

extern "C" void kernel_launch(void* const* d_in, const int* in_sizes, int n_in,
                              void* d_out, int out_size) {
    const int* ei      = (const int*)d_in[0];
    const int* src     = ei;
    const int* dst     = ei + Ee;
    const float* nf    = (const float*)d_in[1];
    const float* ef    = (const float*)d_in[2];
    const int* et_rel  = (const int*)d_in[3];
    const int* et_inv  = (const int*)d_in[4];
    const float* s2r_b = (const float*)d_in[6];
    const float* s2r_a = (const float*)d_in[7];
    const float* o2r_b = (const float*)d_in[8];
    const float* o2r_a = (const float*)d_in[9];
    const float* r2s_b = (const float*)d_in[10];
    const float* r2s_a = (const float*)d_in[11];
    const float* r2s_w = (const float*)d_in[12];
    const float* r2s_bias = (const float*)d_in[13];
    const float* r2o_b = (const float*)d_in[14];
    const float* r2o_a = (const float*)d_in[15];
    const float* r2o_w = (const float*)d_in[16];
    const float* r2o_bias = (const float*)d_in[17];

    float* node_out = (float*)d_out;
    float* rel_out  = node_out + (size_t)Nn*Cc;

    cudaFuncSetAttribute(k_edge, cudaFuncAttributeMaxDynamicSharedMemorySize, SM2_TOTAL);
    cudaFuncSetAttribute(k_g3, cudaFuncAttributeMaxDynamicSharedMemorySize, SM3_TOTAL);

    k_init<<<(2*NK + 255)/256, 256>>>();
    k_w<<<4*Rr*Cc, 256>>>(s2r_b, s2r_a, o2r_b, o2r_a, r2s_b, r2s_a, r2o_b, r2o_a);
    k_wsplit<<<4*Rr*64, 256>>>();
    k_nfsplit<<<(Nn*Cc)/256, 256>>>(nf);
    k_v<<<2*Rr, 256>>>(r2s_w, r2o_w);
    k_hist<<<256, 256>>>(src, dst, et_rel, et_inv);
    k_smallscan<<<1, 32>>>();
    k_binscatter<<<256, 256>>>(et_rel, et_inv);
    k_scan1<<<2*NCHUNK, 256>>>();
    k_scan2<<<1, 32>>>();
    k_scan3<<<2*NCHUNK, 256>>>();
    k_csrscatter<<<Ee/256, 256>>>(src, dst, et_rel, et_inv);
    k_invdiv<<<Nn/256, 256>>>();

    k_edge<<<TILES2, 512, SM2_TOTAL>>>(src, dst, ef, rel_out, r2s_bias, r2o_bias);
    k_pfill<<<2*NK/8, 256>>>(rel_out);
    k_g3<<<Nn/TILE_M, 512, SM3_TOTAL>>>(nf, node_out);
}

// round 9
// speedup vs baseline: 2.7860x; 1.2629x over previous
#include <cuda_runtime.h>
#include <cuda_bf16.h>
#include <math.h>
#include <stdint.h>

#define Nn 16384
#define Ee 262144
#define Cc 256
#define Rr 9
#define Bb 4
#define NK (Nn*Rr)
#define NCHUNK (NK/1024)
#define TILE_M 128
#define NPAIR (Rr*Rr)                 /* 81 */
#define TILES2 (Ee/TILE_M + NPAIR)    /* 2129 */

#define PADK 40                       /* padded bf16 cols per 32-col chunk row */

#define A_BYTES  (128*PADK*2)         /* 10240 */
#define B_BYTES  (256*PADK*2)         /* 20480 */

/* edge kernel smem: AH, AL, BH per stage */
#define SM2_ES   0
#define SM2_GSS  512
#define SM2_GSD  1024
#define SM2_BUF  2048
#define SSTRIDE_E (2*A_BYTES + B_BYTES)    /* 40960 */
#define SM2_TOTAL (SM2_BUF + 2*SSTRIDE_E)  /* 83968 */

/* g3 kernel smem: AH, BH, BL per stage */
#define SSTRIDE_G (A_BYTES + 2*B_BYTES)    /* 51200 */
#define SM3_TOTAL (2*SSTRIDE_G)            /* 102400 */

// ---------------- static scratch ----------------
__device__ float g_W[4][Rr*Cc*Cc];                           // 0:s2r 1:o2r 2:r2s 3:r2o
__device__ __align__(16) __nv_bfloat16 g_Wt_hi[4][Rr*Cc*Cc]; // transposed [n][k]
__device__ __align__(16) __nv_bfloat16 g_Wt_lo[4][Rr*Cc*Cc];
__device__ __align__(16) __nv_bfloat16 g_nf_hi[(size_t)Nn*Cc];
__device__ __align__(16) __nv_bfloat16 g_nf_lo[(size_t)Nn*Cc];
__device__ float g_v[2][Rr*Cc];
__device__ float g_scores[2][Ee];
__device__ int   g_counts[2][NK];
__device__ int   g_rowptr[2][NK+1];
__device__ int   g_cursor[2][NK];
__device__ int   g_elist[2][Ee];
__device__ int   g_partials[2][NCHUNK];
__device__ __align__(16) __nv_bfloat16 g_Ph[2][(size_t)NK*Cc];
__device__ float g_invdiv[2][Nn];
__device__ int   g_pairCount[NPAIR];
__device__ int   g_pairStart[NPAIR+1];
__device__ int   g_tileStart2[NPAIR+1];
__device__ int   g_pairCursor[NPAIR];
__device__ int   g_perm2[Ee];

// ---------------- helpers ----------------
__device__ __forceinline__ uint32_t smem_u32(const void* p){
    return (uint32_t)__cvta_generic_to_shared((void*)p);
}
__device__ __forceinline__ void cpa16(uint32_t d, const void* s){
    asm volatile("cp.async.cg.shared.global [%0], [%1], 16;" :: "r"(d), "l"(s) : "memory");
}
__device__ __forceinline__ void cpa_commit(){
    asm volatile("cp.async.commit_group;" ::: "memory");
}
__device__ __forceinline__ void cpa_wait1(){
    asm volatile("cp.async.wait_group 1;" ::: "memory");
}
__device__ __forceinline__ void cpa_wait0(){
    asm volatile("cp.async.wait_group 0;" ::: "memory");
}
__device__ __forceinline__ void mma16816(float* c, const uint32_t* a, uint32_t b0, uint32_t b1){
    asm volatile("mma.sync.aligned.m16n8k16.row.col.f32.bf16.bf16.f32 "
        "{%0,%1,%2,%3}, {%4,%5,%6,%7}, {%8,%9}, {%0,%1,%2,%3};"
        : "+f"(c[0]), "+f"(c[1]), "+f"(c[2]), "+f"(c[3])
        : "r"(a[0]), "r"(a[1]), "r"(a[2]), "r"(a[3]), "r"(b0), "r"(b1));
}

// ---------------- setup kernels ----------------
__global__ void k_init() {
    int i = blockIdx.x*256 + threadIdx.x;
    if (i < 2*NK) ((int*)g_counts)[i] = 0;
    if (i < NPAIR) g_pairCount[i] = 0;
}

__global__ void k_w(const float* b0, const float* a0, const float* b1, const float* a1,
                    const float* b2, const float* a2, const float* b3, const float* a3) {
    int bx = blockIdx.x;
    int br = bx / (Rr*Cc);
    int rem = bx % (Rr*Cc);
    int r = rem / Cc, i = rem % Cc, j = threadIdx.x;
    const float* bas = (br==0)?b0:(br==1)?b1:(br==2)?b2:b3;
    const float* att = (br==0)?a0:(br==1)?a1:(br==2)?a2:a3;
    float w = 0.f;
#pragma unroll
    for (int b = 0; b < Bb; b++) w += att[r*Bb+b]*bas[(b*Cc+i)*Cc + j];
    g_W[br][(r*Cc+i)*Cc + j] = w;
}

// tiled transpose + split: g_W[br][r][i][j] -> g_Wt_hi/lo[br][r][j*256+i]
__global__ void k_wsplit() {
    __shared__ float t[32][33];
    int bid = blockIdx.x;
    int br = bid / (Rr*64);
    int rem = bid % (Rr*64);
    int r = rem / 64, tile = rem % 64;
    int ti = (tile/8)*32, tj = (tile%8)*32;
    int lx = threadIdx.x & 31, ly = threadIdx.x >> 5;
    const float* W = g_W[br] + r*Cc*Cc;
#pragma unroll
    for (int s = 0; s < 32; s += 8) t[ly+s][lx] = W[(ti+ly+s)*Cc + tj+lx];
    __syncthreads();
    __nv_bfloat16* Wh = g_Wt_hi[br] + r*Cc*Cc;
    __nv_bfloat16* Wl = g_Wt_lo[br] + r*Cc*Cc;
#pragma unroll
    for (int s = 0; s < 32; s += 8) {
        float v = t[lx][ly+s];
        __nv_bfloat16 h = __float2bfloat16(v);
        Wh[(tj+ly+s)*Cc + ti+lx] = h;
        Wl[(tj+ly+s)*Cc + ti+lx] = __float2bfloat16(v - __bfloat162float(h));
    }
}

__global__ void k_nfsplit(const float* nf) {
    int i = blockIdx.x*256 + threadIdx.x;
    float x = nf[i];
    __nv_bfloat16 h = __float2bfloat16(x);
    g_nf_hi[i] = h;
    g_nf_lo[i] = __float2bfloat16(x - __bfloat162float(h));
}

__global__ void k_v(const float* aw_sub, const float* aw_obj) {
    int br = blockIdx.x / Rr, r = blockIdx.x % Rr;
    const float* aw = (br==0) ? aw_sub : aw_obj;
    const float* W = g_W[2+br] + r*Cc*Cc;
    int i = threadIdx.x;
    float s = 0.f;
    for (int j = 0; j < Cc; j++) s += W[i*Cc+j]*aw[r*Cc+j];
    g_v[br][r*Cc+i] = s;
}

// pair hist + per-(node,rel) key counts
__global__ void k_hist(const int* src, const int* dst, const int* et_rel, const int* et_inv) {
    __shared__ int h[NPAIR];
    int tid = threadIdx.x;
    if (tid < NPAIR) h[tid] = 0;
    __syncthreads();
#pragma unroll
    for (int u = 0; u < 4; u++) {
        int e = blockIdx.x*1024 + u*256 + tid;
        int r1 = et_rel[e], r2 = et_inv[e];
        atomicAdd(&h[r1*Rr + r2], 1);
        atomicAdd(&g_counts[0][src[e]*Rr + r2], 1);
        atomicAdd(&g_counts[1][dst[e]*Rr + r1], 1);
    }
    __syncthreads();
    if (tid < NPAIR) atomicAdd(&g_pairCount[tid], h[tid]);
}

__global__ void k_smallscan() {
    if (threadIdx.x == 0) {
        int s = 0, t = 0;
        for (int p = 0; p < NPAIR; p++) {
            g_pairStart[p] = s; g_tileStart2[p] = t; g_pairCursor[p] = s;
            int c = g_pairCount[p];
            s += c; t += (c + TILE_M-1)/TILE_M;
        }
        g_pairStart[NPAIR] = s; g_tileStart2[NPAIR] = t;
    }
}

__global__ void k_binscatter(const int* et_rel, const int* et_inv) {
    __shared__ int h[NPAIR], base[NPAIR], loc[NPAIR];
    int tid = threadIdx.x;
    if (tid < NPAIR) { h[tid] = 0; loc[tid] = 0; }
    __syncthreads();
    int es[4], ps[4];
#pragma unroll
    for (int u = 0; u < 4; u++) {
        int e = blockIdx.x*1024 + u*256 + tid;
        es[u] = e; ps[u] = et_rel[e]*Rr + et_inv[e];
        atomicAdd(&h[ps[u]], 1);
    }
    __syncthreads();
    if (tid < NPAIR) base[tid] = atomicAdd(&g_pairCursor[tid], h[tid]);
    __syncthreads();
#pragma unroll
    for (int u = 0; u < 4; u++) {
        int p = base[ps[u]] + atomicAdd(&loc[ps[u]], 1);
        g_perm2[p] = es[u];
    }
}

__global__ void k_scan1() {
    int br = blockIdx.x / NCHUNK, ch = blockIdx.x % NCHUNK;
    int tid = threadIdx.x;
    int basei = ch*1024 + tid*4;
    int v[4]; int t = 0;
#pragma unroll
    for (int i = 0; i < 4; i++) { v[i] = g_counts[br][basei+i]; t += v[i]; }
    __shared__ int s[256];
    s[tid] = t; __syncthreads();
    for (int off = 1; off < 256; off <<= 1) {
        int x = (tid >= off) ? s[tid-off] : 0;
        __syncthreads();
        s[tid] += x;
        __syncthreads();
    }
    int excl = s[tid] - t;
#pragma unroll
    for (int i = 0; i < 4; i++) { g_rowptr[br][basei+i] = excl; excl += v[i]; }
    if (tid == 255) g_partials[br][ch] = s[255];
}

__global__ void k_scan2() {
    int br = threadIdx.x;
    if (br < 2) {
        int run = 0;
        for (int c = 0; c < NCHUNK; c++) { int p = g_partials[br][c]; g_partials[br][c] = run; run += p; }
        g_rowptr[br][NK] = run;
    }
}

__global__ void k_scan3() {
    int br = blockIdx.x / NCHUNK, ch = blockIdx.x % NCHUNK;
    int add = g_partials[br][ch];
    int basei = ch*1024 + threadIdx.x*4;
#pragma unroll
    for (int i = 0; i < 4; i++) {
        int p = g_rowptr[br][basei+i] + add;
        g_rowptr[br][basei+i] = p;
        g_cursor[br][basei+i] = p;
    }
}

__global__ void k_csrscatter(const int* src, const int* dst, const int* et_rel, const int* et_inv) {
    int e = blockIdx.x*256 + threadIdx.x;
    int k0 = src[e]*Rr + et_inv[e];
    g_elist[0][atomicAdd(&g_cursor[0][k0], 1)] = e;
    int k1 = dst[e]*Rr + et_rel[e];
    g_elist[1][atomicAdd(&g_cursor[1][k1], 1)] = e;
}

__global__ void k_invdiv() {
    int n = blockIdx.x*256 + threadIdx.x;
#pragma unroll
    for (int br = 0; br < 2; br++) {
        int c = 0;
        for (int r = 0; r < Rr; r++)
            if (g_rowptr[br][n*Rr+r+1] > g_rowptr[br][n*Rr+r]) c++;
        g_invdiv[br][n] = c ? 1.f/(float)c : 1.f;
    }
}

// ---------------- fused pair-binned edge GEMM + score ----------------
// rel = ef + 0.5*([nf[src],nf[dst]] @ [W0[r1];W1[r2]])  (K=512), fused leaky-relu scores
// 2-pass: A exact (hi+lo), B rounded bf16 (hi only)
__global__ void __launch_bounds__(512,1) k_edge(const int* __restrict__ src,
        const int* __restrict__ dst, const float* __restrict__ ef,
        float* __restrict__ rel_out,
        const float* __restrict__ bias_sub, const float* __restrict__ bias_obj) {
    extern __shared__ char smem[];
    int bx = blockIdx.x;
    if (bx >= g_tileStart2[NPAIR]) return;
    int pr = 0;
    while (bx >= g_tileStart2[pr+1]) pr++;
    int r1 = pr / Rr, r2 = pr % Rr;
    int row0 = g_pairStart[pr] + (bx - g_tileStart2[pr])*TILE_M;
    int rowEnd = g_pairStart[pr+1];

    int tid = threadIdx.x;
    int* es  = (int*)(smem + SM2_ES);
    int* gsS = (int*)(smem + SM2_GSS);
    int* gsD = (int*)(smem + SM2_GSD);
    if (tid < 128) {
        int row = row0 + tid;
        if (row < rowEnd) { int e = g_perm2[row]; es[tid] = e; gsS[tid] = src[e]; gsD[tid] = dst[e]; }
        else { es[tid] = -1; gsS[tid] = 0; gsD[tid] = 0; }
    }
    __syncthreads();

    const __nv_bfloat16* W1h = g_Wt_hi[0] + (size_t)r1*Cc*Cc;
    const __nv_bfloat16* W2h = g_Wt_hi[1] + (size_t)r2*Cc*Cc;

    auto load_chunk = [&](int ch, int st){
        char* base = smem + SM2_BUF + st*SSTRIDE_E;
        __nv_bfloat16* AH = (__nv_bfloat16*)base;
        __nv_bfloat16* AL = (__nv_bfloat16*)(base + A_BYTES);
        __nv_bfloat16* BH = (__nv_bfloat16*)(base + 2*A_BYTES);
        int srcside = ch < 8;
        int k0 = (ch & 7)*32;
        {
            int row = tid >> 2, c16 = tid & 3;
            int node = srcside ? gsS[row] : gsD[row];
            size_t so = (size_t)node*Cc + k0 + c16*8;
            int dof = row*PADK + c16*8;
            cpa16(smem_u32(AH + dof), g_nf_hi + so);
            cpa16(smem_u32(AL + dof), g_nf_lo + so);
        }
        const __nv_bfloat16* Wh = srcside ? W1h : W2h;
#pragma unroll
        for (int it = 0; it < 2; it++) {
            int i = it*512 + tid; int row = i >> 2, c16 = i & 3;
            size_t so = (size_t)row*Cc + k0 + c16*8;
            int dof = row*PADK + c16*8;
            cpa16(smem_u32(BH + dof), Wh + so);
        }
        cpa_commit();
    };

    int lane = tid & 31, wid = tid >> 5;
    int gid = lane >> 2, tig = lane & 3;
    int wm = wid & 3, wn = wid >> 2;

    float acc[2][8][4];
#pragma unroll
    for (int mt = 0; mt < 2; mt++)
#pragma unroll
        for (int nt = 0; nt < 8; nt++)
#pragma unroll
            for (int q = 0; q < 4; q++) acc[mt][nt][q] = 0.f;

    load_chunk(0, 0);
    for (int ch = 0; ch < 16; ch++) {
        if (ch < 15) { load_chunk(ch+1, (ch+1)&1); cpa_wait1(); }
        else cpa_wait0();
        __syncthreads();
        char* base = smem + SM2_BUF + (ch&1)*SSTRIDE_E;
        const __nv_bfloat16* AH = (const __nv_bfloat16*)base;
        const __nv_bfloat16* AL = (const __nv_bfloat16*)(base + A_BYTES);
        const __nv_bfloat16* BH = (const __nv_bfloat16*)(base + 2*A_BYTES);
#pragma unroll
        for (int ks = 0; ks < 2; ks++) {
            int kc = ks*16 + 2*tig;
            uint32_t ah[2][4], al[2][4];
#pragma unroll
            for (int mt = 0; mt < 2; mt++) {
                int r0 = (wm*32 + mt*16 + gid)*PADK + kc;
                ah[mt][0] = *(const uint32_t*)(AH + r0);
                ah[mt][1] = *(const uint32_t*)(AH + r0 + 8*PADK);
                ah[mt][2] = *(const uint32_t*)(AH + r0 + 8);
                ah[mt][3] = *(const uint32_t*)(AH + r0 + 8*PADK + 8);
                al[mt][0] = *(const uint32_t*)(AL + r0);
                al[mt][1] = *(const uint32_t*)(AL + r0 + 8*PADK);
                al[mt][2] = *(const uint32_t*)(AL + r0 + 8);
                al[mt][3] = *(const uint32_t*)(AL + r0 + 8*PADK + 8);
            }
#pragma unroll
            for (int nt = 0; nt < 8; nt++) {
                int nr = (wn*64 + nt*8 + gid)*PADK + kc;
                uint32_t b0h = *(const uint32_t*)(BH + nr);
                uint32_t b1h = *(const uint32_t*)(BH + nr + 8);
#pragma unroll
                for (int mt = 0; mt < 2; mt++) {
                    mma16816(acc[mt][nt], ah[mt], b0h, b1h);
                    mma16816(acc[mt][nt], al[mt], b0h, b1h);
                }
            }
        }
        __syncthreads();
    }

    // epilogue: rel write + fused scores
    float* sc0 = (float*)(smem + SM2_BUF);
    float* sc1 = sc0 + 128;
    if (tid < 128) { sc0[tid] = 0.f; sc1[tid] = 0.f; }
    __syncthreads();

    const float* vs = g_v[0] + r2*Cc;
    const float* vo = g_v[1] + r1*Cc;
    int cbase = wn*64 + 2*tig;
#pragma unroll
    for (int mt = 0; mt < 2; mt++)
#pragma unroll
        for (int h = 0; h < 2; h++) {
            int row = wm*32 + mt*16 + h*8 + gid;
            int e = es[row];
            float s0 = 0.f, s1 = 0.f;
            if (e >= 0) {
                float* op = rel_out + (size_t)e*Cc + cbase;
                const float* efp = ef + (size_t)e*Cc + cbase;
#pragma unroll
                for (int nt = 0; nt < 8; nt++) {
                    int c = cbase + nt*8;
                    float2 e2 = *(const float2*)(efp + nt*8);
                    float wx = e2.x + 0.5f*acc[mt][nt][h*2+0];
                    float wy = e2.y + 0.5f*acc[mt][nt][h*2+1];
                    *(float2*)(op + nt*8) = make_float2(wx, wy);
                    s0 += wx*vs[c] + wy*vs[c+1];
                    s1 += wx*vo[c] + wy*vo[c+1];
                }
            }
            s0 += __shfl_xor_sync(0xffffffffu, s0, 1);
            s0 += __shfl_xor_sync(0xffffffffu, s0, 2);
            s1 += __shfl_xor_sync(0xffffffffu, s1, 1);
            s1 += __shfl_xor_sync(0xffffffffu, s1, 2);
            if (tig == 0 && e >= 0) {
                atomicAdd(&sc0[row], s0);
                atomicAdd(&sc1[row], s1);
            }
        }
    __syncthreads();
    if (tid < 128) {
        int e = es[tid];
        if (e >= 0) {
            float a = sc0[tid] + bias_sub[r2]; a = (a >= 0.f) ? a : 0.01f*a;
            float b = sc1[tid] + bias_obj[r1]; b = (b >= 0.f) ? b : 0.01f*b;
            g_scores[0][e] = a;
            g_scores[1][e] = b;
        }
    }
}

// P fill (both branches): invdiv-scaled softmax-weighted sums -> bf16 hi only
__global__ void k_pfill(const float* __restrict__ rel) {
    int w = blockIdx.x*8 + (threadIdx.x >> 5);
    int lane = threadIdx.x & 31;
    int br = (w >= NK) ? 1 : 0;
    int key = w - br*NK;
    if (w >= 2*NK) return;
    int lo = g_rowptr[br][key], hi = g_rowptr[br][key+1];
    float acc[8];
#pragma unroll
    for (int i = 0; i < 8; i++) acc[i] = 0.f;
    if (lo < hi) {
        float m = -1e30f;
        for (int p = lo; p < hi; p++) m = fmaxf(m, g_scores[br][g_elist[br][p]]);
        float den = 0.f;
        for (int p = lo; p < hi; p++) {
            int e = g_elist[br][p];
            float wt = expf(g_scores[br][e] - m);
            den += wt;
            const float* x = rel + (size_t)e*Cc;
#pragma unroll
            for (int i = 0; i < 8; i++) acc[i] += wt*x[i*32 + lane];
        }
        float inv = g_invdiv[br][key/Rr]/den;
#pragma unroll
        for (int i = 0; i < 8; i++) acc[i] *= inv;
    }
    __nv_bfloat16* Ph = g_Ph[br] + (size_t)key*Cc;
#pragma unroll
    for (int i = 0; i < 8; i++) Ph[i*32+lane] = __float2bfloat16(acc[i]);
}

// ---------------- fused agg GEMM: out = nf + 0.5*([P0,P1] @ [W2;W3])  (K=4608) ----------------
// 2-pass: A = P rounded bf16 (hi only), B = W exact (hi+lo)
__global__ void __launch_bounds__(512,1) k_g3(const float* __restrict__ nf,
                                              float* __restrict__ node_out) {
    extern __shared__ char smem[];
    int n0 = blockIdx.x*TILE_M;
    int tid = threadIdx.x;

    auto load_chunk = [&](int ch, int st){
        char* base = smem + st*SSTRIDE_G;
        __nv_bfloat16* AH = (__nv_bfloat16*)base;
        __nv_bfloat16* BH = (__nv_bfloat16*)(base + A_BYTES);
        __nv_bfloat16* BL = (__nv_bfloat16*)(base + A_BYTES + B_BYTES);
        int brs = ch >= 72;
        int kk = (brs ? ch-72 : ch)*32;
        {
            int row = tid >> 2, c16 = tid & 3;
            size_t so = (size_t)(n0+row)*(Rr*Cc) + kk + c16*8;
            int dof = row*PADK + c16*8;
            cpa16(smem_u32(AH + dof), g_Ph[brs] + so);
        }
        int rb = kk >> 8, c0 = kk & 255;
        const __nv_bfloat16* Wh = g_Wt_hi[2+brs] + (size_t)rb*Cc*Cc + c0;
        const __nv_bfloat16* Wl = g_Wt_lo[2+brs] + (size_t)rb*Cc*Cc + c0;
#pragma unroll
        for (int it = 0; it < 2; it++) {
            int i = it*512 + tid; int row = i >> 2, c16 = i & 3;
            size_t so = (size_t)row*Cc + c16*8;
            int dof = row*PADK + c16*8;
            cpa16(smem_u32(BH + dof), Wh + so);
            cpa16(smem_u32(BL + dof), Wl + so);
        }
        cpa_commit();
    };

    int lane = tid & 31, wid = tid >> 5;
    int gid = lane >> 2, tig = lane & 3;
    int wm = wid & 3, wn = wid >> 2;

    float acc[2][8][4];
#pragma unroll
    for (int mt = 0; mt < 2; mt++)
#pragma unroll
        for (int nt = 0; nt < 8; nt++)
#pragma unroll
            for (int q = 0; q < 4; q++) acc[mt][nt][q] = 0.f;

    const int NCH = 144;
    load_chunk(0, 0);
    for (int ch = 0; ch < NCH; ch++) {
        if (ch < NCH-1) { load_chunk(ch+1, (ch+1)&1); cpa_wait1(); }
        else cpa_wait0();
        __syncthreads();
        char* base = smem + (ch&1)*SSTRIDE_G;
        const __nv_bfloat16* AH = (const __nv_bfloat16*)base;
        const __nv_bfloat16* BH = (const __nv_bfloat16*)(base + A_BYTES);
        const __nv_bfloat16* BL = (const __nv_bfloat16*)(base + A_BYTES + B_BYTES);
#pragma unroll
        for (int ks = 0; ks < 2; ks++) {
            int kc = ks*16 + 2*tig;
            uint32_t ah[2][4];
#pragma unroll
            for (int mt = 0; mt < 2; mt++) {
                int r0 = (wm*32 + mt*16 + gid)*PADK + kc;
                ah[mt][0] = *(const uint32_t*)(AH + r0);
                ah[mt][1] = *(const uint32_t*)(AH + r0 + 8*PADK);
                ah[mt][2] = *(const uint32_t*)(AH + r0 + 8);
                ah[mt][3] = *(const uint32_t*)(AH + r0 + 8*PADK + 8);
            }
#pragma unroll
            for (int nt = 0; nt < 8; nt++) {
                int nr = (wn*64 + nt*8 + gid)*PADK + kc;
                uint32_t b0h = *(const uint32_t*)(BH + nr);
                uint32_t b1h = *(const uint32_t*)(BH + nr + 8);
                uint32_t b0l = *(const uint32_t*)(BL + nr);
                uint32_t b1l = *(const uint32_t*)(BL + nr + 8);
#pragma unroll
                for (int mt = 0; mt < 2; mt++) {
                    mma16816(acc[mt][nt], ah[mt], b0h, b1h);
                    mma16816(acc[mt][nt], ah[mt], b0l, b1l);
                }
            }
        }
        __syncthreads();
    }

    int cbase = wn*64 + 2*tig;
#pragma unroll
    for (int mt = 0; mt < 2; mt++)
#pragma unroll
        for (int h = 0; h < 2; h++) {
            int n = n0 + wm*32 + mt*16 + h*8 + gid;
            float* op = node_out + (size_t)n*Cc + cbase;
            const float* nfp = nf + (size_t)n*Cc + cbase;
#pragma unroll
            for (int nt = 0; nt < 8; nt++) {
                float2 b2 = *(const float2*)(nfp + nt*8);
                float2 w;
                w.x = b2.x + 0.5f*acc[mt][nt][h*2+0];
                w.y = b2.y + 0.5f*acc[mt][nt][h*2+1];
                *(float2*)(op + nt*8) = w;
            }
        }
}

extern "C" void kernel_launch(void* const* d_in, const int* in_sizes, int n_in,
                              void* d_out, int out_size) {
    const int* ei      = (const int*)d_in[0];
    const int* src     = ei;
    const int* dst     = ei + Ee;
    const float* nf    = (const float*)d_in[1];
    const float* ef    = (const float*)d_in[2];
    const int* et_rel  = (const int*)d_in[3];
    const int* et_inv  = (const int*)d_in[4];
    const float* s2r_b = (const float*)d_in[6];
    const float* s2r_a = (const float*)d_in[7];
    const float* o2r_b = (const float*)d_in[8];
    const float* o2r_a = (const float*)d_in[9];
    const float* r2s_b = (const float*)d_in[10];
    const float* r2s_a = (const float*)d_in[11];
    const float* r2s_w = (const float*)d_in[12];
    const float* r2s_bias = (const float*)d_in[13];
    const float* r2o_b = (const float*)d_in[14];
    const float* r2o_a = (const float*)d_in[15];
    const float* r2o_w = (const float*)d_in[16];
    const float* r2o_bias = (const float*)d_in[17];

    float* node_out = (float*)d_out;
    float* rel_out  = node_out + (size_t)Nn*Cc;

    cudaFuncSetAttribute(k_edge, cudaFuncAttributeMaxDynamicSharedMemorySize, SM2_TOTAL);
    cudaFuncSetAttribute(k_g3, cudaFuncAttributeMaxDynamicSharedMemorySize, SM3_TOTAL);

    k_init<<<(2*NK + 255)/256, 256>>>();
    k_w<<<4*Rr*Cc, 256>>>(s2r_b, s2r_a, o2r_b, o2r_a, r2s_b, r2s_a, r2o_b, r2o_a);
    k_wsplit<<<4*Rr*64, 256>>>();
    k_nfsplit<<<(Nn*Cc)/256, 256>>>(nf);
    k_v<<<2*Rr, 256>>>(r2s_w, r2o_w);
    k_hist<<<256, 256>>>(src, dst, et_rel, et_inv);
    k_smallscan<<<1, 32>>>();
    k_binscatter<<<256, 256>>>(et_rel, et_inv);
    k_scan1<<<2*NCHUNK, 256>>>();
    k_scan2<<<1, 32>>>();
    k_scan3<<<2*NCHUNK, 256>>>();
    k_csrscatter<<<Ee/256, 256>>>(src, dst, et_rel, et_inv);
    k_invdiv<<<Nn/256, 256>>>();

    k_edge<<<TILES2, 512, SM2_TOTAL>>>(src, dst, ef, rel_out, r2s_bias, r2o_bias);
    k_pfill<<<2*NK/8, 256>>>(rel_out);
    k_g3<<<Nn/TILE_M, 512, SM3_TOTAL>>>(nf, node_out);
}

// round 10
// speedup vs baseline: 3.6059x; 1.2943x over previous
#include <cuda_runtime.h>
#include <cuda_bf16.h>
#include <math.h>
#include <stdint.h>

#define Nn 16384
#define Ee 262144
#define Cc 256
#define Rr 9
#define Bb 4
#define NK (Nn*Rr)
#define NCHUNK (NK/1024)
#define TILE_M 128
#define NPAIR (Rr*Rr)                 /* 81 */
#define TILES2 (Ee/TILE_M + NPAIR)    /* 2129 */

#define PADK 40                       /* padded bf16 cols per 32-col chunk row */

#define A_BYTES  (128*PADK*2)         /* 10240 */
#define B_BYTES  (256*PADK*2)         /* 20480 */

/* edge kernel smem: AH, BH per stage */
#define SM2_ES   0
#define SM2_GSS  512
#define SM2_GSD  1024
#define SM2_BUF  2048
#define SSTRIDE_E (A_BYTES + B_BYTES)      /* 30720 */
#define SM2_TOTAL (SM2_BUF + 2*SSTRIDE_E)  /* 63488 */

/* g3 kernel smem: AH, BH per stage */
#define SSTRIDE_G (A_BYTES + B_BYTES)      /* 30720 */
#define SM3_TOTAL (2*SSTRIDE_G)            /* 61440 */

// ---------------- static scratch ----------------
__device__ float g_W[4][Rr*Cc*Cc];                           // 0:s2r 1:o2r 2:r2s 3:r2o
__device__ __align__(16) __nv_bfloat16 g_Wt_hi[4][Rr*Cc*Cc]; // transposed [n][k]
__device__ __align__(16) __nv_bfloat16 g_nf_hi[(size_t)Nn*Cc];
__device__ float g_v[2][Rr*Cc];
__device__ float g_scores[2][Ee];
__device__ int   g_counts[2][NK];
__device__ int   g_rowptr[2][NK+1];
__device__ int   g_cursor[2][NK];
__device__ int   g_elist[2][Ee];
__device__ int   g_partials[2][NCHUNK];
__device__ __align__(16) __nv_bfloat16 g_Ph[2][(size_t)NK*Cc];
__device__ float g_invdiv[2][Nn];
__device__ int   g_pairCount[NPAIR];
__device__ int   g_pairStart[NPAIR+1];
__device__ int   g_tileStart2[NPAIR+1];
__device__ int   g_pairCursor[NPAIR];
__device__ int   g_perm2[Ee];

// ---------------- helpers ----------------
__device__ __forceinline__ uint32_t smem_u32(const void* p){
    return (uint32_t)__cvta_generic_to_shared((void*)p);
}
__device__ __forceinline__ void cpa16(uint32_t d, const void* s){
    asm volatile("cp.async.cg.shared.global [%0], [%1], 16;" :: "r"(d), "l"(s) : "memory");
}
__device__ __forceinline__ void cpa_commit(){
    asm volatile("cp.async.commit_group;" ::: "memory");
}
__device__ __forceinline__ void cpa_wait1(){
    asm volatile("cp.async.wait_group 1;" ::: "memory");
}
__device__ __forceinline__ void cpa_wait0(){
    asm volatile("cp.async.wait_group 0;" ::: "memory");
}
__device__ __forceinline__ void mma16816(float* c, const uint32_t* a, uint32_t b0, uint32_t b1){
    asm volatile("mma.sync.aligned.m16n8k16.row.col.f32.bf16.bf16.f32 "
        "{%0,%1,%2,%3}, {%4,%5,%6,%7}, {%8,%9}, {%0,%1,%2,%3};"
        : "+f"(c[0]), "+f"(c[1]), "+f"(c[2]), "+f"(c[3])
        : "r"(a[0]), "r"(a[1]), "r"(a[2]), "r"(a[3]), "r"(b0), "r"(b1));
}

// ---------------- setup kernels ----------------
__global__ void k_init() {
    int i = blockIdx.x*256 + threadIdx.x;
    if (i < 2*NK) ((int*)g_counts)[i] = 0;
    if (i < NPAIR) g_pairCount[i] = 0;
}

__global__ void k_w(const float* b0, const float* a0, const float* b1, const float* a1,
                    const float* b2, const float* a2, const float* b3, const float* a3) {
    int bx = blockIdx.x;
    int br = bx / (Rr*Cc);
    int rem = bx % (Rr*Cc);
    int r = rem / Cc, i = rem % Cc, j = threadIdx.x;
    const float* bas = (br==0)?b0:(br==1)?b1:(br==2)?b2:b3;
    const float* att = (br==0)?a0:(br==1)?a1:(br==2)?a2:a3;
    float w = 0.f;
#pragma unroll
    for (int b = 0; b < Bb; b++) w += att[r*Bb+b]*bas[(b*Cc+i)*Cc + j];
    g_W[br][(r*Cc+i)*Cc + j] = w;
}

// tiled transpose + round: g_W[br][r][i][j] -> g_Wt_hi[br][r][j*256+i]
__global__ void k_wsplit() {
    __shared__ float t[32][33];
    int bid = blockIdx.x;
    int br = bid / (Rr*64);
    int rem = bid % (Rr*64);
    int r = rem / 64, tile = rem % 64;
    int ti = (tile/8)*32, tj = (tile%8)*32;
    int lx = threadIdx.x & 31, ly = threadIdx.x >> 5;
    const float* W = g_W[br] + r*Cc*Cc;
#pragma unroll
    for (int s = 0; s < 32; s += 8) t[ly+s][lx] = W[(ti+ly+s)*Cc + tj+lx];
    __syncthreads();
    __nv_bfloat16* Wh = g_Wt_hi[br] + r*Cc*Cc;
#pragma unroll
    for (int s = 0; s < 32; s += 8)
        Wh[(tj+ly+s)*Cc + ti+lx] = __float2bfloat16(t[lx][ly+s]);
}

__global__ void k_nfsplit(const float* nf) {
    int i = blockIdx.x*256 + threadIdx.x;
    g_nf_hi[i] = __float2bfloat16(nf[i]);
}

__global__ void k_v(const float* aw_sub, const float* aw_obj) {
    int br = blockIdx.x / Rr, r = blockIdx.x % Rr;
    const float* aw = (br==0) ? aw_sub : aw_obj;
    const float* W = g_W[2+br] + r*Cc*Cc;
    int i = threadIdx.x;
    float s = 0.f;
    for (int j = 0; j < Cc; j++) s += W[i*Cc+j]*aw[r*Cc+j];
    g_v[br][r*Cc+i] = s;
}

// pair hist + per-(node,rel) key counts
__global__ void k_hist(const int* src, const int* dst, const int* et_rel, const int* et_inv) {
    __shared__ int h[NPAIR];
    int tid = threadIdx.x;
    if (tid < NPAIR) h[tid] = 0;
    __syncthreads();
#pragma unroll
    for (int u = 0; u < 4; u++) {
        int e = blockIdx.x*1024 + u*256 + tid;
        int r1 = et_rel[e], r2 = et_inv[e];
        atomicAdd(&h[r1*Rr + r2], 1);
        atomicAdd(&g_counts[0][src[e]*Rr + r2], 1);
        atomicAdd(&g_counts[1][dst[e]*Rr + r1], 1);
    }
    __syncthreads();
    if (tid < NPAIR) atomicAdd(&g_pairCount[tid], h[tid]);
}

__global__ void k_smallscan() {
    if (threadIdx.x == 0) {
        int s = 0, t = 0;
        for (int p = 0; p < NPAIR; p++) {
            g_pairStart[p] = s; g_tileStart2[p] = t; g_pairCursor[p] = s;
            int c = g_pairCount[p];
            s += c; t += (c + TILE_M-1)/TILE_M;
        }
        g_pairStart[NPAIR] = s; g_tileStart2[NPAIR] = t;
    }
}

__global__ void k_binscatter(const int* et_rel, const int* et_inv) {
    __shared__ int h[NPAIR], base[NPAIR], loc[NPAIR];
    int tid = threadIdx.x;
    if (tid < NPAIR) { h[tid] = 0; loc[tid] = 0; }
    __syncthreads();
    int es[4], ps[4];
#pragma unroll
    for (int u = 0; u < 4; u++) {
        int e = blockIdx.x*1024 + u*256 + tid;
        es[u] = e; ps[u] = et_rel[e]*Rr + et_inv[e];
        atomicAdd(&h[ps[u]], 1);
    }
    __syncthreads();
    if (tid < NPAIR) base[tid] = atomicAdd(&g_pairCursor[tid], h[tid]);
    __syncthreads();
#pragma unroll
    for (int u = 0; u < 4; u++) {
        int p = base[ps[u]] + atomicAdd(&loc[ps[u]], 1);
        g_perm2[p] = es[u];
    }
}

__global__ void k_scan1() {
    int br = blockIdx.x / NCHUNK, ch = blockIdx.x % NCHUNK;
    int tid = threadIdx.x;
    int basei = ch*1024 + tid*4;
    int v[4]; int t = 0;
#pragma unroll
    for (int i = 0; i < 4; i++) { v[i] = g_counts[br][basei+i]; t += v[i]; }
    __shared__ int s[256];
    s[tid] = t; __syncthreads();
    for (int off = 1; off < 256; off <<= 1) {
        int x = (tid >= off) ? s[tid-off] : 0;
        __syncthreads();
        s[tid] += x;
        __syncthreads();
    }
    int excl = s[tid] - t;
#pragma unroll
    for (int i = 0; i < 4; i++) { g_rowptr[br][basei+i] = excl; excl += v[i]; }
    if (tid == 255) g_partials[br][ch] = s[255];
}

__global__ void k_scan2() {
    int br = threadIdx.x;
    if (br < 2) {
        int run = 0;
        for (int c = 0; c < NCHUNK; c++) { int p = g_partials[br][c]; g_partials[br][c] = run; run += p; }
        g_rowptr[br][NK] = run;
    }
}

__global__ void k_scan3() {
    int br = blockIdx.x / NCHUNK, ch = blockIdx.x % NCHUNK;
    int add = g_partials[br][ch];
    int basei = ch*1024 + threadIdx.x*4;
#pragma unroll
    for (int i = 0; i < 4; i++) {
        int p = g_rowptr[br][basei+i] + add;
        g_rowptr[br][basei+i] = p;
        g_cursor[br][basei+i] = p;
    }
}

__global__ void k_csrscatter(const int* src, const int* dst, const int* et_rel, const int* et_inv) {
    int e = blockIdx.x*256 + threadIdx.x;
    int k0 = src[e]*Rr + et_inv[e];
    g_elist[0][atomicAdd(&g_cursor[0][k0], 1)] = e;
    int k1 = dst[e]*Rr + et_rel[e];
    g_elist[1][atomicAdd(&g_cursor[1][k1], 1)] = e;
}

__global__ void k_invdiv() {
    int n = blockIdx.x*256 + threadIdx.x;
#pragma unroll
    for (int br = 0; br < 2; br++) {
        int c = 0;
        for (int r = 0; r < Rr; r++)
            if (g_rowptr[br][n*Rr+r+1] > g_rowptr[br][n*Rr+r]) c++;
        g_invdiv[br][n] = c ? 1.f/(float)c : 1.f;
    }
}

// ---------------- fused pair-binned edge GEMM + score ----------------
// rel = ef + 0.5*([nf[src],nf[dst]] @ [W0[r1];W1[r2]])  (K=512), fused leaky-relu scores
// single-pass bf16
__global__ void __launch_bounds__(512,1) k_edge(const int* __restrict__ src,
        const int* __restrict__ dst, const float* __restrict__ ef,
        float* __restrict__ rel_out,
        const float* __restrict__ bias_sub, const float* __restrict__ bias_obj) {
    extern __shared__ char smem[];
    int bx = blockIdx.x;
    if (bx >= g_tileStart2[NPAIR]) return;
    int pr = 0;
    while (bx >= g_tileStart2[pr+1]) pr++;
    int r1 = pr / Rr, r2 = pr % Rr;
    int row0 = g_pairStart[pr] + (bx - g_tileStart2[pr])*TILE_M;
    int rowEnd = g_pairStart[pr+1];

    int tid = threadIdx.x;
    int* es  = (int*)(smem + SM2_ES);
    int* gsS = (int*)(smem + SM2_GSS);
    int* gsD = (int*)(smem + SM2_GSD);
    if (tid < 128) {
        int row = row0 + tid;
        if (row < rowEnd) { int e = g_perm2[row]; es[tid] = e; gsS[tid] = src[e]; gsD[tid] = dst[e]; }
        else { es[tid] = -1; gsS[tid] = 0; gsD[tid] = 0; }
    }
    __syncthreads();

    const __nv_bfloat16* W1h = g_Wt_hi[0] + (size_t)r1*Cc*Cc;
    const __nv_bfloat16* W2h = g_Wt_hi[1] + (size_t)r2*Cc*Cc;

    auto load_chunk = [&](int ch, int st){
        char* base = smem + SM2_BUF + st*SSTRIDE_E;
        __nv_bfloat16* AH = (__nv_bfloat16*)base;
        __nv_bfloat16* BH = (__nv_bfloat16*)(base + A_BYTES);
        int srcside = ch < 8;
        int k0 = (ch & 7)*32;
        {
            int row = tid >> 2, c16 = tid & 3;
            int node = srcside ? gsS[row] : gsD[row];
            size_t so = (size_t)node*Cc + k0 + c16*8;
            int dof = row*PADK + c16*8;
            cpa16(smem_u32(AH + dof), g_nf_hi + so);
        }
        const __nv_bfloat16* Wh = srcside ? W1h : W2h;
#pragma unroll
        for (int it = 0; it < 2; it++) {
            int i = it*512 + tid; int row = i >> 2, c16 = i & 3;
            size_t so = (size_t)row*Cc + k0 + c16*8;
            int dof = row*PADK + c16*8;
            cpa16(smem_u32(BH + dof), Wh + so);
        }
        cpa_commit();
    };

    int lane = tid & 31, wid = tid >> 5;
    int gid = lane >> 2, tig = lane & 3;
    int wm = wid & 3, wn = wid >> 2;

    float acc[2][8][4];
#pragma unroll
    for (int mt = 0; mt < 2; mt++)
#pragma unroll
        for (int nt = 0; nt < 8; nt++)
#pragma unroll
            for (int q = 0; q < 4; q++) acc[mt][nt][q] = 0.f;

    load_chunk(0, 0);
    for (int ch = 0; ch < 16; ch++) {
        if (ch < 15) { load_chunk(ch+1, (ch+1)&1); cpa_wait1(); }
        else cpa_wait0();
        __syncthreads();
        char* base = smem + SM2_BUF + (ch&1)*SSTRIDE_E;
        const __nv_bfloat16* AH = (const __nv_bfloat16*)base;
        const __nv_bfloat16* BH = (const __nv_bfloat16*)(base + A_BYTES);
#pragma unroll
        for (int ks = 0; ks < 2; ks++) {
            int kc = ks*16 + 2*tig;
            uint32_t ah[2][4];
#pragma unroll
            for (int mt = 0; mt < 2; mt++) {
                int r0 = (wm*32 + mt*16 + gid)*PADK + kc;
                ah[mt][0] = *(const uint32_t*)(AH + r0);
                ah[mt][1] = *(const uint32_t*)(AH + r0 + 8*PADK);
                ah[mt][2] = *(const uint32_t*)(AH + r0 + 8);
                ah[mt][3] = *(const uint32_t*)(AH + r0 + 8*PADK + 8);
            }
#pragma unroll
            for (int nt = 0; nt < 8; nt++) {
                int nr = (wn*64 + nt*8 + gid)*PADK + kc;
                uint32_t b0h = *(const uint32_t*)(BH + nr);
                uint32_t b1h = *(const uint32_t*)(BH + nr + 8);
#pragma unroll
                for (int mt = 0; mt < 2; mt++)
                    mma16816(acc[mt][nt], ah[mt], b0h, b1h);
            }
        }
        __syncthreads();
    }

    // epilogue: rel write + fused scores
    float* sc0 = (float*)(smem + SM2_BUF);
    float* sc1 = sc0 + 128;
    if (tid < 128) { sc0[tid] = 0.f; sc1[tid] = 0.f; }
    __syncthreads();

    const float* vs = g_v[0] + r2*Cc;
    const float* vo = g_v[1] + r1*Cc;
    int cbase = wn*64 + 2*tig;
#pragma unroll
    for (int mt = 0; mt < 2; mt++)
#pragma unroll
        for (int h = 0; h < 2; h++) {
            int row = wm*32 + mt*16 + h*8 + gid;
            int e = es[row];
            float s0 = 0.f, s1 = 0.f;
            if (e >= 0) {
                float* op = rel_out + (size_t)e*Cc + cbase;
                const float* efp = ef + (size_t)e*Cc + cbase;
#pragma unroll
                for (int nt = 0; nt < 8; nt++) {
                    int c = cbase + nt*8;
                    float2 e2 = *(const float2*)(efp + nt*8);
                    float wx = e2.x + 0.5f*acc[mt][nt][h*2+0];
                    float wy = e2.y + 0.5f*acc[mt][nt][h*2+1];
                    *(float2*)(op + nt*8) = make_float2(wx, wy);
                    s0 += wx*vs[c] + wy*vs[c+1];
                    s1 += wx*vo[c] + wy*vo[c+1];
                }
            }
            s0 += __shfl_xor_sync(0xffffffffu, s0, 1);
            s0 += __shfl_xor_sync(0xffffffffu, s0, 2);
            s1 += __shfl_xor_sync(0xffffffffu, s1, 1);
            s1 += __shfl_xor_sync(0xffffffffu, s1, 2);
            if (tig == 0 && e >= 0) {
                atomicAdd(&sc0[row], s0);
                atomicAdd(&sc1[row], s1);
            }
        }
    __syncthreads();
    if (tid < 128) {
        int e = es[tid];
        if (e >= 0) {
            float a = sc0[tid] + bias_sub[r2]; a = (a >= 0.f) ? a : 0.01f*a;
            float b = sc1[tid] + bias_obj[r1]; b = (b >= 0.f) ? b : 0.01f*b;
            g_scores[0][e] = a;
            g_scores[1][e] = b;
        }
    }
}

// P fill (both branches): invdiv-scaled softmax-weighted sums -> bf16
__global__ void k_pfill(const float* __restrict__ rel) {
    int w = blockIdx.x*8 + (threadIdx.x >> 5);
    int lane = threadIdx.x & 31;
    int br = (w >= NK) ? 1 : 0;
    int key = w - br*NK;
    if (w >= 2*NK) return;
    int lo = g_rowptr[br][key], hi = g_rowptr[br][key+1];
    float acc[8];
#pragma unroll
    for (int i = 0; i < 8; i++) acc[i] = 0.f;
    if (lo < hi) {
        float m = -1e30f;
        for (int p = lo; p < hi; p++) m = fmaxf(m, g_scores[br][g_elist[br][p]]);
        float den = 0.f;
        for (int p = lo; p < hi; p++) {
            int e = g_elist[br][p];
            float wt = expf(g_scores[br][e] - m);
            den += wt;
            const float* x = rel + (size_t)e*Cc;
#pragma unroll
            for (int i = 0; i < 8; i++) acc[i] += wt*x[i*32 + lane];
        }
        float inv = g_invdiv[br][key/Rr]/den;
#pragma unroll
        for (int i = 0; i < 8; i++) acc[i] *= inv;
    }
    __nv_bfloat16* Ph = g_Ph[br] + (size_t)key*Cc;
#pragma unroll
    for (int i = 0; i < 8; i++) Ph[i*32+lane] = __float2bfloat16(acc[i]);
}

// ---------------- fused agg GEMM: out = nf + 0.5*([P0,P1] @ [W2;W3])  (K=4608) ----------------
// single-pass bf16
__global__ void __launch_bounds__(512,1) k_g3(const float* __restrict__ nf,
                                              float* __restrict__ node_out) {
    extern __shared__ char smem[];
    int n0 = blockIdx.x*TILE_M;
    int tid = threadIdx.x;

    auto load_chunk = [&](int ch, int st){
        char* base = smem + st*SSTRIDE_G;
        __nv_bfloat16* AH = (__nv_bfloat16*)base;
        __nv_bfloat16* BH = (__nv_bfloat16*)(base + A_BYTES);
        int brs = ch >= 72;
        int kk = (brs ? ch-72 : ch)*32;
        {
            int row = tid >> 2, c16 = tid & 3;
            size_t so = (size_t)(n0+row)*(Rr*Cc) + kk + c16*8;
            int dof = row*PADK + c16*8;
            cpa16(smem_u32(AH + dof), g_Ph[brs] + so);
        }
        int rb = kk >> 8, c0 = kk & 255;
        const __nv_bfloat16* Wh = g_Wt_hi[2+brs] + (size_t)rb*Cc*Cc + c0;
#pragma unroll
        for (int it = 0; it < 2; it++) {
            int i = it*512 + tid; int row = i >> 2, c16 = i & 3;
            size_t so = (size_t)row*Cc + c16*8;
            int dof = row*PADK + c16*8;
            cpa16(smem_u32(BH + dof), Wh + so);
        }
        cpa_commit();
    };

    int lane = tid & 31, wid = tid >> 5;
    int gid = lane >> 2, tig = lane & 3;
    int wm = wid & 3, wn = wid >> 2;

    float acc[2][8][4];
#pragma unroll
    for (int mt = 0; mt < 2; mt++)
#pragma unroll
        for (int nt = 0; nt < 8; nt++)
#pragma unroll
            for (int q = 0; q < 4; q++) acc[mt][nt][q] = 0.f;

    const int NCH = 144;
    load_chunk(0, 0);
    for (int ch = 0; ch < NCH; ch++) {
        if (ch < NCH-1) { load_chunk(ch+1, (ch+1)&1); cpa_wait1(); }
        else cpa_wait0();
        __syncthreads();
        char* base = smem + (ch&1)*SSTRIDE_G;
        const __nv_bfloat16* AH = (const __nv_bfloat16*)base;
        const __nv_bfloat16* BH = (const __nv_bfloat16*)(base + A_BYTES);
#pragma unroll
        for (int ks = 0; ks < 2; ks++) {
            int kc = ks*16 + 2*tig;
            uint32_t ah[2][4];
#pragma unroll
            for (int mt = 0; mt < 2; mt++) {
                int r0 = (wm*32 + mt*16 + gid)*PADK + kc;
                ah[mt][0] = *(const uint32_t*)(AH + r0);
                ah[mt][1] = *(const uint32_t*)(AH + r0 + 8*PADK);
                ah[mt][2] = *(const uint32_t*)(AH + r0 + 8);
                ah[mt][3] = *(const uint32_t*)(AH + r0 + 8*PADK + 8);
            }
#pragma unroll
            for (int nt = 0; nt < 8; nt++) {
                int nr = (wn*64 + nt*8 + gid)*PADK + kc;
                uint32_t b0h = *(const uint32_t*)(BH + nr);
                uint32_t b1h = *(const uint32_t*)(BH + nr + 8);
#pragma unroll
                for (int mt = 0; mt < 2; mt++)
                    mma16816(acc[mt][nt], ah[mt], b0h, b1h);
            }
        }
        __syncthreads();
    }

    int cbase = wn*64 + 2*tig;
#pragma unroll
    for (int mt = 0; mt < 2; mt++)
#pragma unroll
        for (int h = 0; h < 2; h++) {
            int n = n0 + wm*32 + mt*16 + h*8 + gid;
            float* op = node_out + (size_t)n*Cc + cbase;
            const float* nfp = nf + (size_t)n*Cc + cbase;
#pragma unroll
            for (int nt = 0; nt < 8; nt++) {
                float2 b2 = *(const float2*)(nfp + nt*8);
                float2 w;
                w.x = b2.x + 0.5f*acc[mt][nt][h*2+0];
                w.y = b2.y + 0.5f*acc[mt][nt][h*2+1];
                *(float2*)(op + nt*8) = w;
            }
        }
}

extern "C" void kernel_launch(void* const* d_in, const int* in_sizes, int n_in,
                              void* d_out, int out_size) {
    const int* ei      = (const int*)d_in[0];
    const int* src     = ei;
    const int* dst     = ei + Ee;
    const float* nf    = (const float*)d_in[1];
    const float* ef    = (const float*)d_in[2];
    const int* et_rel  = (const int*)d_in[3];
    const int* et_inv  = (const int*)d_in[4];
    const float* s2r_b = (const float*)d_in[6];
    const float* s2r_a = (const float*)d_in[7];
    const float* o2r_b = (const float*)d_in[8];
    const float* o2r_a = (const float*)d_in[9];
    const float* r2s_b = (const float*)d_in[10];
    const float* r2s_a = (const float*)d_in[11];
    const float* r2s_w = (const float*)d_in[12];
    const float* r2s_bias = (const float*)d_in[13];
    const float* r2o_b = (const float*)d_in[14];
    const float* r2o_a = (const float*)d_in[15];
    const float* r2o_w = (const float*)d_in[16];
    const float* r2o_bias = (const float*)d_in[17];

    float* node_out = (float*)d_out;
    float* rel_out  = node_out + (size_t)Nn*Cc;

    cudaFuncSetAttribute(k_edge, cudaFuncAttributeMaxDynamicSharedMemorySize, SM2_TOTAL);
    cudaFuncSetAttribute(k_g3, cudaFuncAttributeMaxDynamicSharedMemorySize, SM3_TOTAL);

    k_init<<<(2*NK + 255)/256, 256>>>();
    k_w<<<4*Rr*Cc, 256>>>(s2r_b, s2r_a, o2r_b, o2r_a, r2s_b, r2s_a, r2o_b, r2o_a);
    k_wsplit<<<4*Rr*64, 256>>>();
    k_nfsplit<<<(Nn*Cc)/256, 256>>>(nf);
    k_v<<<2*Rr, 256>>>(r2s_w, r2o_w);
    k_hist<<<256, 256>>>(src, dst, et_rel, et_inv);
    k_smallscan<<<1, 32>>>();
    k_binscatter<<<256, 256>>>(et_rel, et_inv);
    k_scan1<<<2*NCHUNK, 256>>>();
    k_scan2<<<1, 32>>>();
    k_scan3<<<2*NCHUNK, 256>>>();
    k_csrscatter<<<Ee/256, 256>>>(src, dst, et_rel, et_inv);
    k_invdiv<<<Nn/256, 256>>>();

    k_edge<<<TILES2, 512, SM2_TOTAL>>>(src, dst, ef, rel_out, r2s_bias, r2o_bias);
    k_pfill<<<2*NK/8, 256>>>(rel_out);
    k_g3<<<Nn/TILE_M, 512, SM3_TOTAL>>>(nf, node_out);
}

// round 11
// speedup vs baseline: 3.6380x; 1.0089x over previous
#include <cuda_runtime.h>
#include <cuda_bf16.h>
#include <math.h>
#include <stdint.h>

#define Nn 16384
#define Ee 262144
#define Cc 256
#define Rr 9
#define Bb 4
#define NK (Nn*Rr)
#define NCHUNK (NK/1024)
#define TILE_M 128
#define NPAIR (Rr*Rr)                 /* 81 */
#define TILES2 (Ee/TILE_M + NPAIR)    /* 2129 */

#define PADK 40                       /* padded bf16 cols per 32-col chunk row */

#define A_BYTES  (128*PADK*2)         /* 10240 */
#define B_BYTES  (256*PADK*2)         /* 20480 */

/* edge kernel smem: AH, BH per stage */
#define SM2_ES   0
#define SM2_GSS  512
#define SM2_GSD  1024
#define SM2_BUF  2048
#define SSTRIDE_E (A_BYTES + B_BYTES)      /* 30720 */
#define SM2_TOTAL (SM2_BUF + 2*SSTRIDE_E)  /* 63488 */

/* g3 kernel smem: AH, BH per stage */
#define SSTRIDE_G (A_BYTES + B_BYTES)      /* 30720 */
#define SM3_TOTAL (2*SSTRIDE_G)            /* 61440 */

// ---------------- static scratch ----------------
__device__ float g_W[4][Rr*Cc*Cc];                           // 0:s2r 1:o2r 2:r2s 3:r2o
__device__ __align__(16) __nv_bfloat16 g_Wt_hi[4][Rr*Cc*Cc]; // transposed [n][k]
__device__ __align__(16) __nv_bfloat16 g_nf_hi[(size_t)Nn*Cc];
__device__ __align__(16) __nv_bfloat16 g_relb[(size_t)Ee*Cc]; // bf16 mirror of rel_emb
__device__ float g_v[2][Rr*Cc];
__device__ float g_scores[2][Ee];
__device__ int   g_counts[2][NK];
__device__ int   g_rowptr[2][NK+1];
__device__ int   g_cursor[2][NK];
__device__ int   g_elist[2][Ee];
__device__ int   g_partials[2][NCHUNK];
__device__ __align__(16) __nv_bfloat16 g_Ph[2][(size_t)NK*Cc];
__device__ float g_invdiv[2][Nn];
__device__ int   g_pairCount[NPAIR];
__device__ int   g_pairStart[NPAIR+1];
__device__ int   g_tileStart2[NPAIR+1];
__device__ int   g_pairCursor[NPAIR];
__device__ int   g_perm2[Ee];

// ---------------- helpers ----------------
__device__ __forceinline__ uint32_t smem_u32(const void* p){
    return (uint32_t)__cvta_generic_to_shared((void*)p);
}
__device__ __forceinline__ void cpa16(uint32_t d, const void* s){
    asm volatile("cp.async.cg.shared.global [%0], [%1], 16;" :: "r"(d), "l"(s) : "memory");
}
__device__ __forceinline__ void cpa_commit(){
    asm volatile("cp.async.commit_group;" ::: "memory");
}
__device__ __forceinline__ void cpa_wait1(){
    asm volatile("cp.async.wait_group 1;" ::: "memory");
}
__device__ __forceinline__ void cpa_wait0(){
    asm volatile("cp.async.wait_group 0;" ::: "memory");
}
__device__ __forceinline__ void mma16816(float* c, const uint32_t* a, uint32_t b0, uint32_t b1){
    asm volatile("mma.sync.aligned.m16n8k16.row.col.f32.bf16.bf16.f32 "
        "{%0,%1,%2,%3}, {%4,%5,%6,%7}, {%8,%9}, {%0,%1,%2,%3};"
        : "+f"(c[0]), "+f"(c[1]), "+f"(c[2]), "+f"(c[3])
        : "r"(a[0]), "r"(a[1]), "r"(a[2]), "r"(a[3]), "r"(b0), "r"(b1));
}
__device__ __forceinline__ void ldsm4(uint32_t* r, uint32_t addr){
    asm volatile("ldmatrix.sync.aligned.m8n8.x4.shared.b16 {%0,%1,%2,%3}, [%4];"
        : "=r"(r[0]), "=r"(r[1]), "=r"(r[2]), "=r"(r[3]) : "r"(addr));
}

// ---------------- setup kernels ----------------
__global__ void k_init() {
    int i = blockIdx.x*256 + threadIdx.x;
    if (i < 2*NK) ((int*)g_counts)[i] = 0;
    if (i < NPAIR) g_pairCount[i] = 0;
}

__global__ void k_w(const float* b0, const float* a0, const float* b1, const float* a1,
                    const float* b2, const float* a2, const float* b3, const float* a3) {
    int bx = blockIdx.x;
    int br = bx / (Rr*Cc);
    int rem = bx % (Rr*Cc);
    int r = rem / Cc, i = rem % Cc, j = threadIdx.x;
    const float* bas = (br==0)?b0:(br==1)?b1:(br==2)?b2:b3;
    const float* att = (br==0)?a0:(br==1)?a1:(br==2)?a2:a3;
    float w = 0.f;
#pragma unroll
    for (int b = 0; b < Bb; b++) w += att[r*Bb+b]*bas[(b*Cc+i)*Cc + j];
    g_W[br][(r*Cc+i)*Cc + j] = w;
}

// tiled transpose + round: g_W[br][r][i][j] -> g_Wt_hi[br][r][j*256+i]
__global__ void k_wsplit() {
    __shared__ float t[32][33];
    int bid = blockIdx.x;
    int br = bid / (Rr*64);
    int rem = bid % (Rr*64);
    int r = rem / 64, tile = rem % 64;
    int ti = (tile/8)*32, tj = (tile%8)*32;
    int lx = threadIdx.x & 31, ly = threadIdx.x >> 5;
    const float* W = g_W[br] + r*Cc*Cc;
#pragma unroll
    for (int s = 0; s < 32; s += 8) t[ly+s][lx] = W[(ti+ly+s)*Cc + tj+lx];
    __syncthreads();
    __nv_bfloat16* Wh = g_Wt_hi[br] + r*Cc*Cc;
#pragma unroll
    for (int s = 0; s < 32; s += 8)
        Wh[(tj+ly+s)*Cc + ti+lx] = __float2bfloat16(t[lx][ly+s]);
}

__global__ void k_nfsplit(const float* nf) {
    int i = blockIdx.x*256 + threadIdx.x;
    g_nf_hi[i] = __float2bfloat16(nf[i]);
}

__global__ void k_v(const float* aw_sub, const float* aw_obj) {
    int br = blockIdx.x / Rr, r = blockIdx.x % Rr;
    const float* aw = (br==0) ? aw_sub : aw_obj;
    const float* W = g_W[2+br] + r*Cc*Cc;
    int i = threadIdx.x;
    float s = 0.f;
    for (int j = 0; j < Cc; j++) s += W[i*Cc+j]*aw[r*Cc+j];
    g_v[br][r*Cc+i] = s;
}

// pair hist + per-(node,rel) key counts
__global__ void k_hist(const int* src, const int* dst, const int* et_rel, const int* et_inv) {
    __shared__ int h[NPAIR];
    int tid = threadIdx.x;
    if (tid < NPAIR) h[tid] = 0;
    __syncthreads();
#pragma unroll
    for (int u = 0; u < 4; u++) {
        int e = blockIdx.x*1024 + u*256 + tid;
        int r1 = et_rel[e], r2 = et_inv[e];
        atomicAdd(&h[r1*Rr + r2], 1);
        atomicAdd(&g_counts[0][src[e]*Rr + r2], 1);
        atomicAdd(&g_counts[1][dst[e]*Rr + r1], 1);
    }
    __syncthreads();
    if (tid < NPAIR) atomicAdd(&g_pairCount[tid], h[tid]);
}

__global__ void k_smallscan() {
    if (threadIdx.x == 0) {
        int s = 0, t = 0;
        for (int p = 0; p < NPAIR; p++) {
            g_pairStart[p] = s; g_tileStart2[p] = t; g_pairCursor[p] = s;
            int c = g_pairCount[p];
            s += c; t += (c + TILE_M-1)/TILE_M;
        }
        g_pairStart[NPAIR] = s; g_tileStart2[NPAIR] = t;
    }
}

__global__ void k_binscatter(const int* et_rel, const int* et_inv) {
    __shared__ int h[NPAIR], base[NPAIR], loc[NPAIR];
    int tid = threadIdx.x;
    if (tid < NPAIR) { h[tid] = 0; loc[tid] = 0; }
    __syncthreads();
    int es[4], ps[4];
#pragma unroll
    for (int u = 0; u < 4; u++) {
        int e = blockIdx.x*1024 + u*256 + tid;
        es[u] = e; ps[u] = et_rel[e]*Rr + et_inv[e];
        atomicAdd(&h[ps[u]], 1);
    }
    __syncthreads();
    if (tid < NPAIR) base[tid] = atomicAdd(&g_pairCursor[tid], h[tid]);
    __syncthreads();
#pragma unroll
    for (int u = 0; u < 4; u++) {
        int p = base[ps[u]] + atomicAdd(&loc[ps[u]], 1);
        g_perm2[p] = es[u];
    }
}

__global__ void k_scan1() {
    int br = blockIdx.x / NCHUNK, ch = blockIdx.x % NCHUNK;
    int tid = threadIdx.x;
    int basei = ch*1024 + tid*4;
    int v[4]; int t = 0;
#pragma unroll
    for (int i = 0; i < 4; i++) { v[i] = g_counts[br][basei+i]; t += v[i]; }
    __shared__ int s[256];
    s[tid] = t; __syncthreads();
    for (int off = 1; off < 256; off <<= 1) {
        int x = (tid >= off) ? s[tid-off] : 0;
        __syncthreads();
        s[tid] += x;
        __syncthreads();
    }
    int excl = s[tid] - t;
#pragma unroll
    for (int i = 0; i < 4; i++) { g_rowptr[br][basei+i] = excl; excl += v[i]; }
    if (tid == 255) g_partials[br][ch] = s[255];
}

__global__ void k_scan2() {
    int br = threadIdx.x;
    if (br < 2) {
        int run = 0;
        for (int c = 0; c < NCHUNK; c++) { int p = g_partials[br][c]; g_partials[br][c] = run; run += p; }
        g_rowptr[br][NK] = run;
    }
}

__global__ void k_scan3() {
    int br = blockIdx.x / NCHUNK, ch = blockIdx.x % NCHUNK;
    int add = g_partials[br][ch];
    int basei = ch*1024 + threadIdx.x*4;
#pragma unroll
    for (int i = 0; i < 4; i++) {
        int p = g_rowptr[br][basei+i] + add;
        g_rowptr[br][basei+i] = p;
        g_cursor[br][basei+i] = p;
    }
}

__global__ void k_csrscatter(const int* src, const int* dst, const int* et_rel, const int* et_inv) {
    int e = blockIdx.x*256 + threadIdx.x;
    int k0 = src[e]*Rr + et_inv[e];
    g_elist[0][atomicAdd(&g_cursor[0][k0], 1)] = e;
    int k1 = dst[e]*Rr + et_rel[e];
    g_elist[1][atomicAdd(&g_cursor[1][k1], 1)] = e;
}

__global__ void k_invdiv() {
    int n = blockIdx.x*256 + threadIdx.x;
#pragma unroll
    for (int br = 0; br < 2; br++) {
        int c = 0;
        for (int r = 0; r < Rr; r++)
            if (g_rowptr[br][n*Rr+r+1] > g_rowptr[br][n*Rr+r]) c++;
        g_invdiv[br][n] = c ? 1.f/(float)c : 1.f;
    }
}

// ---------------- fused pair-binned edge GEMM + score ----------------
// rel = ef + 0.5*([nf[src],nf[dst]] @ [W0[r1];W1[r2]])  (K=512), fused leaky-relu scores
// single-pass bf16, ldmatrix fragment loads
__global__ void __launch_bounds__(512,1) k_edge(const int* __restrict__ src,
        const int* __restrict__ dst, const float* __restrict__ ef,
        float* __restrict__ rel_out,
        const float* __restrict__ bias_sub, const float* __restrict__ bias_obj) {
    extern __shared__ char smem[];
    int bx = blockIdx.x;
    if (bx >= g_tileStart2[NPAIR]) return;
    int pr = 0;
    while (bx >= g_tileStart2[pr+1]) pr++;
    int r1 = pr / Rr, r2 = pr % Rr;
    int row0 = g_pairStart[pr] + (bx - g_tileStart2[pr])*TILE_M;
    int rowEnd = g_pairStart[pr+1];

    int tid = threadIdx.x;
    int* es  = (int*)(smem + SM2_ES);
    int* gsS = (int*)(smem + SM2_GSS);
    int* gsD = (int*)(smem + SM2_GSD);
    if (tid < 128) {
        int row = row0 + tid;
        if (row < rowEnd) { int e = g_perm2[row]; es[tid] = e; gsS[tid] = src[e]; gsD[tid] = dst[e]; }
        else { es[tid] = -1; gsS[tid] = 0; gsD[tid] = 0; }
    }
    __syncthreads();

    const __nv_bfloat16* W1h = g_Wt_hi[0] + (size_t)r1*Cc*Cc;
    const __nv_bfloat16* W2h = g_Wt_hi[1] + (size_t)r2*Cc*Cc;

    auto load_chunk = [&](int ch, int st){
        char* base = smem + SM2_BUF + st*SSTRIDE_E;
        __nv_bfloat16* AH = (__nv_bfloat16*)base;
        __nv_bfloat16* BH = (__nv_bfloat16*)(base + A_BYTES);
        int srcside = ch < 8;
        int k0 = (ch & 7)*32;
        {
            int row = tid >> 2, c16 = tid & 3;
            int node = srcside ? gsS[row] : gsD[row];
            size_t so = (size_t)node*Cc + k0 + c16*8;
            int dof = row*PADK + c16*8;
            cpa16(smem_u32(AH + dof), g_nf_hi + so);
        }
        const __nv_bfloat16* Wh = srcside ? W1h : W2h;
#pragma unroll
        for (int it = 0; it < 2; it++) {
            int i = it*512 + tid; int row = i >> 2, c16 = i & 3;
            size_t so = (size_t)row*Cc + k0 + c16*8;
            int dof = row*PADK + c16*8;
            cpa16(smem_u32(BH + dof), Wh + so);
        }
        cpa_commit();
    };

    int lane = tid & 31, wid = tid >> 5;
    int gid = lane >> 2, tig = lane & 3;
    int wm = wid & 3, wn = wid >> 2;

    /* ldmatrix lane address components */
    int a_row = (lane & 15);                    /* + wm*32 + mt*16 */
    int a_koff = (lane >> 4) << 3;
    int b_row = (lane & 7) + (((lane >> 4) & 1) << 3);  /* + wn*64 + ntp*16 */
    int b_koff = ((lane >> 3) & 1) << 3;

    float acc[2][8][4];
#pragma unroll
    for (int mt = 0; mt < 2; mt++)
#pragma unroll
        for (int nt = 0; nt < 8; nt++)
#pragma unroll
            for (int q = 0; q < 4; q++) acc[mt][nt][q] = 0.f;

    load_chunk(0, 0);
    for (int ch = 0; ch < 16; ch++) {
        if (ch < 15) { load_chunk(ch+1, (ch+1)&1); cpa_wait1(); }
        else cpa_wait0();
        __syncthreads();
        char* base = smem + SM2_BUF + (ch&1)*SSTRIDE_E;
        uint32_t aA = smem_u32(base);
        uint32_t aB = smem_u32(base + A_BYTES);
#pragma unroll
        for (int ks = 0; ks < 2; ks++) {
            int kc = ks*16;
            uint32_t ah[2][4];
#pragma unroll
            for (int mt = 0; mt < 2; mt++)
                ldsm4(ah[mt], aA + ((wm*32 + mt*16 + a_row)*PADK + kc + a_koff)*2);
            uint32_t bb[8][2];
#pragma unroll
            for (int ntp = 0; ntp < 4; ntp++) {
                uint32_t r[4];
                ldsm4(r, aB + ((wn*64 + ntp*16 + b_row)*PADK + kc + b_koff)*2);
                bb[2*ntp][0] = r[0]; bb[2*ntp][1] = r[1];
                bb[2*ntp+1][0] = r[2]; bb[2*ntp+1][1] = r[3];
            }
#pragma unroll
            for (int nt = 0; nt < 8; nt++)
#pragma unroll
                for (int mt = 0; mt < 2; mt++)
                    mma16816(acc[mt][nt], ah[mt], bb[nt][0], bb[nt][1]);
        }
        __syncthreads();
    }

    // epilogue: rel write (fp32 + bf16 mirror) + fused scores
    float* sc0 = (float*)(smem + SM2_BUF);
    float* sc1 = sc0 + 128;
    if (tid < 128) { sc0[tid] = 0.f; sc1[tid] = 0.f; }
    __syncthreads();

    const float* vs = g_v[0] + r2*Cc;
    const float* vo = g_v[1] + r1*Cc;
    int cbase = wn*64 + 2*tig;
#pragma unroll
    for (int mt = 0; mt < 2; mt++)
#pragma unroll
        for (int h = 0; h < 2; h++) {
            int row = wm*32 + mt*16 + h*8 + gid;
            int e = es[row];
            float s0 = 0.f, s1 = 0.f;
            if (e >= 0) {
                float* op = rel_out + (size_t)e*Cc + cbase;
                const float* efp = ef + (size_t)e*Cc + cbase;
                __nv_bfloat16* rb = g_relb + (size_t)e*Cc + cbase;
#pragma unroll
                for (int nt = 0; nt < 8; nt++) {
                    int c = cbase + nt*8;
                    float2 e2 = *(const float2*)(efp + nt*8);
                    float wx = e2.x + 0.5f*acc[mt][nt][h*2+0];
                    float wy = e2.y + 0.5f*acc[mt][nt][h*2+1];
                    *(float2*)(op + nt*8) = make_float2(wx, wy);
                    *(__nv_bfloat162*)(rb + nt*8) = __floats2bfloat162_rn(wx, wy);
                    s0 += wx*vs[c] + wy*vs[c+1];
                    s1 += wx*vo[c] + wy*vo[c+1];
                }
            }
            s0 += __shfl_xor_sync(0xffffffffu, s0, 1);
            s0 += __shfl_xor_sync(0xffffffffu, s0, 2);
            s1 += __shfl_xor_sync(0xffffffffu, s1, 1);
            s1 += __shfl_xor_sync(0xffffffffu, s1, 2);
            if (tig == 0 && e >= 0) {
                atomicAdd(&sc0[row], s0);
                atomicAdd(&sc1[row], s1);
            }
        }
    __syncthreads();
    if (tid < 128) {
        int e = es[tid];
        if (e >= 0) {
            float a = sc0[tid] + bias_sub[r2]; a = (a >= 0.f) ? a : 0.01f*a;
            float b = sc1[tid] + bias_obj[r1]; b = (b >= 0.f) ? b : 0.01f*b;
            g_scores[0][e] = a;
            g_scores[1][e] = b;
        }
    }
}

// P fill (both branches): invdiv-scaled softmax-weighted sums from bf16 rel, single pass
__global__ void k_pfill() {
    int w = blockIdx.x*8 + (threadIdx.x >> 5);
    int lane = threadIdx.x & 31;
    int br = (w >= NK) ? 1 : 0;
    int key = w - br*NK;
    if (w >= 2*NK) return;
    int lo = g_rowptr[br][key], hi = g_rowptr[br][key+1];
    float2 acc[4];
#pragma unroll
    for (int j = 0; j < 4; j++) acc[j] = make_float2(0.f, 0.f);
    if (lo < hi) {
        float den = 0.f;
        for (int p = lo; p < hi; p++) {
            int e = g_elist[br][p];
            float wt = expf(g_scores[br][e]);
            den += wt;
            const __nv_bfloat162* x = (const __nv_bfloat162*)(g_relb + (size_t)e*Cc);
#pragma unroll
            for (int j = 0; j < 4; j++) {
                __nv_bfloat162 v = x[lane + 32*j];
                acc[j].x += wt*__low2float(v);
                acc[j].y += wt*__high2float(v);
            }
        }
        float inv = g_invdiv[br][key/Rr]/den;
#pragma unroll
        for (int j = 0; j < 4; j++) { acc[j].x *= inv; acc[j].y *= inv; }
    }
    __nv_bfloat162* Ph = (__nv_bfloat162*)(g_Ph[br] + (size_t)key*Cc);
#pragma unroll
    for (int j = 0; j < 4; j++) Ph[lane + 32*j] = __floats2bfloat162_rn(acc[j].x, acc[j].y);
}

// ---------------- fused agg GEMM: out = nf + 0.5*([P0,P1] @ [W2;W3])  (K=4608) ----------------
// single-pass bf16, ldmatrix fragment loads
__global__ void __launch_bounds__(512,1) k_g3(const float* __restrict__ nf,
                                              float* __restrict__ node_out) {
    extern __shared__ char smem[];
    int n0 = blockIdx.x*TILE_M;
    int tid = threadIdx.x;

    auto load_chunk = [&](int ch, int st){
        char* base = smem + st*SSTRIDE_G;
        __nv_bfloat16* AH = (__nv_bfloat16*)base;
        __nv_bfloat16* BH = (__nv_bfloat16*)(base + A_BYTES);
        int brs = ch >= 72;
        int kk = (brs ? ch-72 : ch)*32;
        {
            int row = tid >> 2, c16 = tid & 3;
            size_t so = (size_t)(n0+row)*(Rr*Cc) + kk + c16*8;
            int dof = row*PADK + c16*8;
            cpa16(smem_u32(AH + dof), g_Ph[brs] + so);
        }
        int rb = kk >> 8, c0 = kk & 255;
        const __nv_bfloat16* Wh = g_Wt_hi[2+brs] + (size_t)rb*Cc*Cc + c0;
#pragma unroll
        for (int it = 0; it < 2; it++) {
            int i = it*512 + tid; int row = i >> 2, c16 = i & 3;
            size_t so = (size_t)row*Cc + c16*8;
            int dof = row*PADK + c16*8;
            cpa16(smem_u32(BH + dof), Wh + so);
        }
        cpa_commit();
    };

    int lane = tid & 31, wid = tid >> 5;
    int gid = lane >> 2, tig = lane & 3;
    int wm = wid & 3, wn = wid >> 2;

    int a_row = (lane & 15);
    int a_koff = (lane >> 4) << 3;
    int b_row = (lane & 7) + (((lane >> 4) & 1) << 3);
    int b_koff = ((lane >> 3) & 1) << 3;

    float acc[2][8][4];
#pragma unroll
    for (int mt = 0; mt < 2; mt++)
#pragma unroll
        for (int nt = 0; nt < 8; nt++)
#pragma unroll
            for (int q = 0; q < 4; q++) acc[mt][nt][q] = 0.f;

    const int NCH = 144;
    load_chunk(0, 0);
    for (int ch = 0; ch < NCH; ch++) {
        if (ch < NCH-1) { load_chunk(ch+1, (ch+1)&1); cpa_wait1(); }
        else cpa_wait0();
        __syncthreads();
        char* base = smem + (ch&1)*SSTRIDE_G;
        uint32_t aA = smem_u32(base);
        uint32_t aB = smem_u32(base + A_BYTES);
#pragma unroll
        for (int ks = 0; ks < 2; ks++) {
            int kc = ks*16;
            uint32_t ah[2][4];
#pragma unroll
            for (int mt = 0; mt < 2; mt++)
                ldsm4(ah[mt], aA + ((wm*32 + mt*16 + a_row)*PADK + kc + a_koff)*2);
            uint32_t bb[8][2];
#pragma unroll
            for (int ntp = 0; ntp < 4; ntp++) {
                uint32_t r[4];
                ldsm4(r, aB + ((wn*64 + ntp*16 + b_row)*PADK + kc + b_koff)*2);
                bb[2*ntp][0] = r[0]; bb[2*ntp][1] = r[1];
                bb[2*ntp+1][0] = r[2]; bb[2*ntp+1][1] = r[3];
            }
#pragma unroll
            for (int nt = 0; nt < 8; nt++)
#pragma unroll
                for (int mt = 0; mt < 2; mt++)
                    mma16816(acc[mt][nt], ah[mt], bb[nt][0], bb[nt][1]);
        }
        __syncthreads();
    }

    int cbase = wn*64 + 2*tig;
#pragma unroll
    for (int mt = 0; mt < 2; mt++)
#pragma unroll
        for (int h = 0; h < 2; h++) {
            int n = n0 + wm*32 + mt*16 + h*8 + gid;
            float* op = node_out + (size_t)n*Cc + cbase;
            const float* nfp = nf + (size_t)n*Cc + cbase;
#pragma unroll
            for (int nt = 0; nt < 8; nt++) {
                float2 b2 = *(const float2*)(nfp + nt*8);
                float2 w;
                w.x = b2.x + 0.5f*acc[mt][nt][h*2+0];
                w.y = b2.y + 0.5f*acc[mt][nt][h*2+1];
                *(float2*)(op + nt*8) = w;
            }
        }
}

extern "C" void kernel_launch(void* const* d_in, const int* in_sizes, int n_in,
                              void* d_out, int out_size) {
    const int* ei      = (const int*)d_in[0];
    const int* src     = ei;
    const int* dst     = ei + Ee;
    const float* nf    = (const float*)d_in[1];
    const float* ef    = (const float*)d_in[2];
    const int* et_rel  = (const int*)d_in[3];
    const int* et_inv  = (const int*)d_in[4];
    const float* s2r_b = (const float*)d_in[6];
    const float* s2r_a = (const float*)d_in[7];
    const float* o2r_b = (const float*)d_in[8];
    const float* o2r_a = (const float*)d_in[9];
    const float* r2s_b = (const float*)d_in[10];
    const float* r2s_a = (const float*)d_in[11];
    const float* r2s_w = (const float*)d_in[12];
    const float* r2s_bias = (const float*)d_in[13];
    const float* r2o_b = (const float*)d_in[14];
    const float* r2o_a = (const float*)d_in[15];
    const float* r2o_w = (const float*)d_in[16];
    const float* r2o_bias = (const float*)d_in[17];

    float* node_out = (float*)d_out;
    float* rel_out  = node_out + (size_t)Nn*Cc;

    cudaFuncSetAttribute(k_edge, cudaFuncAttributeMaxDynamicSharedMemorySize, SM2_TOTAL);
    cudaFuncSetAttribute(k_g3, cudaFuncAttributeMaxDynamicSharedMemorySize, SM3_TOTAL);

    k_init<<<(2*NK + 255)/256, 256>>>();
    k_w<<<4*Rr*Cc, 256>>>(s2r_b, s2r_a, o2r_b, o2r_a, r2s_b, r2s_a, r2o_b, r2o_a);
    k_wsplit<<<4*Rr*64, 256>>>();
    k_nfsplit<<<(Nn*Cc)/256, 256>>>(nf);
    k_v<<<2*Rr, 256>>>(r2s_w, r2o_w);
    k_hist<<<256, 256>>>(src, dst, et_rel, et_inv);
    k_smallscan<<<1, 32>>>();
    k_binscatter<<<256, 256>>>(et_rel, et_inv);
    k_scan1<<<2*NCHUNK, 256>>>();
    k_scan2<<<1, 32>>>();
    k_scan3<<<2*NCHUNK, 256>>>();
    k_csrscatter<<<Ee/256, 256>>>(src, dst, et_rel, et_inv);
    k_invdiv<<<Nn/256, 256>>>();

    k_edge<<<TILES2, 512, SM2_TOTAL>>>(src, dst, ef, rel_out, r2s_bias, r2o_bias);
    k_pfill<<<2*NK/8, 256>>>();
    k_g3<<<Nn/TILE_M, 512, SM3_TOTAL>>>(nf, node_out);
}